// round 3
// baseline (speedup 1.0000x reference)
#include <cuda_runtime.h>
#include <cuda_bf16.h>

// ---------------------------------------------------------------------------
// Problem constants
// ---------------------------------------------------------------------------
#define BZ   2
#define SQ   2048
#define DM   1024
#define NH   16
#define DH   64
#define FFD  4096
#define MROWS (BZ * SQ)            // 4096

// ---------------------------------------------------------------------------
// Scratch (device globals; no allocations allowed). 112 MB total.
//   g_a: q   -> ctx (flash writes own rows after reading) -> y2 (FF2 out)
//   g_b: k   -> y  (attn out + resid)
//   g_c: v   -> x1 (LN1 out, FF2 residual)
//   g_f: ffh
// ---------------------------------------------------------------------------
__device__ float g_a[(size_t)MROWS * DM];              // 16 MB
__device__ float g_b[(size_t)MROWS * DM];              // 16 MB
__device__ float g_c[(size_t)MROWS * DM];              // 16 MB
__device__ float g_f[(size_t)MROWS * FFD];             // 64 MB

// ---------------------------------------------------------------------------
// Block reduction helper (for LayerNorm)
// ---------------------------------------------------------------------------
__device__ __forceinline__ float block_reduce_sum(float v) {
    __shared__ float sh[32];
    const unsigned mask = 0xffffffffu;
    #pragma unroll
    for (int o = 16; o > 0; o >>= 1) v += __shfl_xor_sync(mask, v, o);
    int lane = threadIdx.x & 31, w = threadIdx.x >> 5;
    __syncthreads();
    if (lane == 0) sh[w] = v;
    __syncthreads();
    int nw = (blockDim.x + 31) >> 5;
    if (w == 0) {
        v = (lane < nw) ? sh[lane] : 0.0f;
        #pragma unroll
        for (int o = 16; o > 0; o >>= 1) v += __shfl_xor_sync(mask, v, o);
        if (lane == 0) sh[0] = v;
    }
    __syncthreads();
    return sh[0];
}

// ---------------------------------------------------------------------------
// SGEMM (TN): C = A @ B^T [+ bias] [+ resid], optional ReLU.
// A: [M,K] row-major, B: [N,K] row-major, C: [M,N]. All dims divide tiles.
// float4-vectorized tile loads (K multiple of BK=16, rows 16B-aligned).
// ---------------------------------------------------------------------------
template<int BM, int BN, int BK, int TM, int TN, bool RELU, bool RESID>
__global__ void __launch_bounds__(256)
gemm_tn(const float* __restrict__ A, int lda,
        const float* __restrict__ B, int ldb,
        const float* __restrict__ bias,
        const float* __restrict__ resid,
        float* __restrict__ C, int ldc,
        int M, int N, int K)
{
    constexpr int THREADS = (BM / TM) * (BN / TN);
    static_assert(THREADS == 256, "block must be 256 threads");
    constexpr int KV = BK / 4;                 // float4s per tile row

    __shared__ float As[BK][BM + 4];
    __shared__ float Bs[BK][BN + 4];

    const int tid = threadIdx.x;
    const int tx  = tid % (BN / TN);
    const int ty  = tid / (BN / TN);
    const int row0 = blockIdx.y * BM;
    const int col0 = blockIdx.x * BN;

    float acc[TM][TN];
    #pragma unroll
    for (int i = 0; i < TM; i++)
        #pragma unroll
        for (int j = 0; j < TN; j++) acc[i][j] = 0.0f;

    for (int k0 = 0; k0 < K; k0 += BK) {
        // A tile: BM*KV float4 loads, scattered transposed into As
        #pragma unroll
        for (int i = tid; i < BM * KV; i += THREADS) {
            int r = i / KV, c = i % KV;
            float4 t = *(const float4*)&A[(long)(row0 + r) * lda + k0 + c * 4];
            As[c * 4 + 0][r] = t.x;
            As[c * 4 + 1][r] = t.y;
            As[c * 4 + 2][r] = t.z;
            As[c * 4 + 3][r] = t.w;
        }
        #pragma unroll
        for (int i = tid; i < BN * KV; i += THREADS) {
            int n = i / KV, c = i % KV;
            float4 t = *(const float4*)&B[(long)(col0 + n) * ldb + k0 + c * 4];
            Bs[c * 4 + 0][n] = t.x;
            Bs[c * 4 + 1][n] = t.y;
            Bs[c * 4 + 2][n] = t.z;
            Bs[c * 4 + 3][n] = t.w;
        }
        __syncthreads();

        #pragma unroll
        for (int kk = 0; kk < BK; kk++) {
            float a[TM], b[TN];
            #pragma unroll
            for (int i = 0; i < TM; i++) a[i] = As[kk][ty * TM + i];
            #pragma unroll
            for (int j = 0; j < TN; j++) b[j] = Bs[kk][tx * TN + j];
            #pragma unroll
            for (int i = 0; i < TM; i++)
                #pragma unroll
                for (int j = 0; j < TN; j++)
                    acc[i][j] = fmaf(a[i], b[j], acc[i][j]);
        }
        __syncthreads();
    }

    #pragma unroll
    for (int i = 0; i < TM; i++) {
        int gr = row0 + ty * TM + i;
        #pragma unroll
        for (int j = 0; j < TN; j++) {
            int gn = col0 + tx * TN + j;
            float vv = acc[i][j];
            if (bias) vv += bias[gn];
            if (RESID) vv += resid[(long)gr * ldc + gn];
            if (RELU)  vv = fmaxf(vv, 0.0f);
            C[(long)gr * ldc + gn] = vv;
        }
    }
}

// ---------------------------------------------------------------------------
// Fused flash attention, fp32. Q/K/V/O: [B*S, H*DH] row-major.
// 256 threads handle BR=64 query rows of one (b,h); 32 KV tiles of BC=64
// with online softmax. O may alias Q: each block reads only its own Q
// rows/head-columns (into SMEM, up front) and writes exactly those back.
// ---------------------------------------------------------------------------
#define SWZ(row, col) ((col) ^ ((row) & 31))

__global__ void __launch_bounds__(256)
flash_attn(const float* __restrict__ Q, const float* __restrict__ K,
           const float* __restrict__ V, float* __restrict__ O)
{
    __shared__ float Qs[64][64];   // [d][r], swizzled
    __shared__ float KVs[64][64];  // K phase: [d][c] swizzled; V phase: [c][d]
    __shared__ float Ps[64][64];   // [c][r], swizzled

    const int bh = blockIdx.y;                // b*NH + h
    const int b  = bh / NH, h = bh % NH;
    const int q0 = blockIdx.x * 64;
    const long base = (long)b * SQ * DM + (long)h * DH;

    const int tid = threadIdx.x;
    const int tx  = tid % 16;     // key / dv partition
    const int ty  = tid / 16;     // query partition

    #pragma unroll
    for (int idx = tid; idx < 64 * 64; idx += 256) {
        int r = idx >> 6, d = idx & 63;
        Qs[d][SWZ(d, r)] = Q[base + (long)(q0 + r) * DM + d];
    }

    float m[4], l[4], o[4][4];
    #pragma unroll
    for (int i = 0; i < 4; i++) {
        m[i] = -3.402823e38f; l[i] = 0.0f;
        #pragma unroll
        for (int j = 0; j < 4; j++) o[i][j] = 0.0f;
    }
    __syncthreads();

    for (int c0 = 0; c0 < SQ; c0 += 64) {
        #pragma unroll
        for (int idx = tid; idx < 64 * 64; idx += 256) {
            int c = idx >> 6, d = idx & 63;
            KVs[d][SWZ(d, c)] = K[base + (long)(c0 + c) * DM + d];
        }
        __syncthreads();

        float s[4][4];
        #pragma unroll
        for (int i = 0; i < 4; i++)
            #pragma unroll
            for (int j = 0; j < 4; j++) s[i][j] = 0.0f;

        #pragma unroll
        for (int d = 0; d < 64; d++) {
            float a[4], bb[4];
            #pragma unroll
            for (int i = 0; i < 4; i++) a[i]  = Qs[d][SWZ(d, ty * 4 + i)];
            #pragma unroll
            for (int j = 0; j < 4; j++) bb[j] = KVs[d][SWZ(d, tx * 4 + j)];
            #pragma unroll
            for (int i = 0; i < 4; i++)
                #pragma unroll
                for (int j = 0; j < 4; j++)
                    s[i][j] = fmaf(a[i], bb[j], s[i][j]);
        }

        // online softmax (scale 1/sqrt(64) = 0.125); row spread over 16 lanes
        #pragma unroll
        for (int i = 0; i < 4; i++) {
            float mt = fmaxf(fmaxf(s[i][0], s[i][1]), fmaxf(s[i][2], s[i][3])) * 0.125f;
            #pragma unroll
            for (int off = 8; off > 0; off >>= 1)
                mt = fmaxf(mt, __shfl_xor_sync(0xffffffffu, mt, off, 16));
            float mnew = fmaxf(m[i], mt);
            float corr = __expf(m[i] - mnew);
            float rs = 0.0f;
            #pragma unroll
            for (int j = 0; j < 4; j++) {
                float p = __expf(s[i][j] * 0.125f - mnew);
                Ps[tx * 4 + j][SWZ(tx * 4 + j, ty * 4 + i)] = p;
                rs += p;
            }
            #pragma unroll
            for (int off = 8; off > 0; off >>= 1)
                rs += __shfl_xor_sync(0xffffffffu, rs, off, 16);
            l[i] = l[i] * corr + rs;
            m[i] = mnew;
            #pragma unroll
            for (int j = 0; j < 4; j++) o[i][j] *= corr;
        }
        __syncthreads();

        #pragma unroll
        for (int idx = tid; idx < 64 * 64; idx += 256) {
            int c = idx >> 6, d = idx & 63;
            KVs[c][d] = V[base + (long)(c0 + c) * DM + d];
        }
        __syncthreads();

        #pragma unroll
        for (int c = 0; c < 64; c++) {
            float a[4], bb[4];
            #pragma unroll
            for (int i = 0; i < 4; i++) a[i]  = Ps[c][SWZ(c, ty * 4 + i)];
            #pragma unroll
            for (int j = 0; j < 4; j++) bb[j] = KVs[c][tx * 4 + j];
            #pragma unroll
            for (int i = 0; i < 4; i++)
                #pragma unroll
                for (int j = 0; j < 4; j++)
                    o[i][j] = fmaf(a[i], bb[j], o[i][j]);
        }
        __syncthreads();
    }

    #pragma unroll
    for (int i = 0; i < 4; i++) {
        const float inv = 1.0f / l[i];
        #pragma unroll
        for (int j = 0; j < 4; j++)
            O[base + (long)(q0 + ty * 4 + i) * DM + (tx * 4 + j)] = o[i][j] * inv;
    }
}

// ---------------------------------------------------------------------------
// LayerNorm over rows of length 1024
// ---------------------------------------------------------------------------
__global__ void __launch_bounds__(256)
layernorm1024(const float* __restrict__ x, const float* __restrict__ g,
              const float* __restrict__ b, float* __restrict__ out)
{
    const long row = blockIdx.x;
    const float* p = x + row * (long)DM;
    float v[4];
    float s = 0.0f;
    #pragma unroll
    for (int i = 0; i < 4; i++) {
        v[i] = p[threadIdx.x + i * 256];
        s += v[i];
    }
    s = block_reduce_sum(s);
    const float mean = s * (1.0f / DM);
    float s2 = 0.0f;
    #pragma unroll
    for (int i = 0; i < 4; i++) {
        float d = v[i] - mean;
        s2 += d * d;
    }
    s2 = block_reduce_sum(s2);
    const float rstd = rsqrtf(s2 * (1.0f / DM) + 1e-5f);
    #pragma unroll
    for (int i = 0; i < 4; i++) {
        int c = threadIdx.x + i * 256;
        out[row * (long)DM + c] = (v[i] - mean) * rstd * g[c] + b[c];
    }
}

// ---------------------------------------------------------------------------
// Launch orchestration (graph-capturable: kernel launches only)
// ---------------------------------------------------------------------------
extern "C" void kernel_launch(void* const* d_in, const int* in_sizes, int n_in,
                              void* d_out, int out_size)
{
    const float* src   = (const float*)d_in[0];
    const float* qw    = (const float*)d_in[1];
    const float* qb    = (const float*)d_in[2];
    const float* kw    = (const float*)d_in[3];
    const float* kb    = (const float*)d_in[4];
    const float* vw    = (const float*)d_in[5];
    const float* vb    = (const float*)d_in[6];
    const float* ow    = (const float*)d_in[7];
    const float* ob    = (const float*)d_in[8];
    const float* w1    = (const float*)d_in[9];
    const float* b1    = (const float*)d_in[10];
    const float* w2    = (const float*)d_in[11];
    const float* b2    = (const float*)d_in[12];
    const float* g1    = (const float*)d_in[13];
    const float* beta1 = (const float*)d_in[14];
    const float* g2    = (const float*)d_in[15];
    const float* beta2 = (const float*)d_in[16];
    float* out = (float*)d_out;

    float *ga, *gb, *gc, *gf;
    cudaGetSymbolAddress((void**)&ga, g_a);
    cudaGetSymbolAddress((void**)&gb, g_b);
    cudaGetSymbolAddress((void**)&gc, g_c);
    cudaGetSymbolAddress((void**)&gf, g_f);

    const dim3 blk(256);

    // ---- QKV projections: q->ga, k->gb, v->gc
    {
        dim3 g(DM / 128, MROWS / 128);
        gemm_tn<128,128,16,8,8,false,false><<<g, blk>>>(
            src, DM, qw, DM, qb, nullptr, ga, DM, MROWS, DM, DM);
        gemm_tn<128,128,16,8,8,false,false><<<g, blk>>>(
            src, DM, kw, DM, kb, nullptr, gb, DM, MROWS, DM, DM);
        gemm_tn<128,128,16,8,8,false,false><<<g, blk>>>(
            src, DM, vw, DM, vb, nullptr, gc, DM, MROWS, DM, DM);
    }

    // ---- fused attention: ctx = softmax(QK^T/8) V  (ctx aliases q in ga)
    {
        dim3 g(SQ / 64, BZ * NH);
        flash_attn<<<g, blk>>>(ga, gb, gc, ga);
    }

    // ---- O projection + residual: y(gb) = ctx(ga) @ ow^T + ob + src
    {
        dim3 g(DM / 128, MROWS / 128);
        gemm_tn<128,128,16,8,8,false,true><<<g, blk>>>(
            ga, DM, ow, DM, ob, src, gb, DM, MROWS, DM, DM);
    }

    // ---- LN1: x1(gc) = LN(y)
    layernorm1024<<<MROWS, blk>>>(gb, g1, beta1, gc);

    // ---- FF1: ffh(gf) = relu(x1 @ w1^T + b1)
    {
        dim3 g(FFD / 128, MROWS / 128);
        gemm_tn<128,128,16,8,8,true,false><<<g, blk>>>(
            gc, DM, w1, DM, b1, nullptr, gf, FFD, MROWS, FFD, DM);
    }

    // ---- FF2 + residual: y2(ga) = ffh @ w2^T + b2 + x1(gc)
    {
        dim3 g(DM / 128, MROWS / 128);
        gemm_tn<128,128,16,8,8,false,true><<<g, blk>>>(
            gf, FFD, w2, FFD, b2, gc, ga, DM, MROWS, DM, FFD);
    }

    // ---- LN2 -> output
    layernorm1024<<<MROWS, blk>>>(ga, g2, beta2, out);
}

// round 5
// speedup vs baseline: 1.9191x; 1.9191x over previous
#include <cuda_runtime.h>
#include <cuda_fp16.h>
#include <cstdint>

// ---------------------------------------------------------------------------
// Problem constants
// ---------------------------------------------------------------------------
#define BZ   2
#define SQ   2048
#define DM   1024
#define NH   16
#define DH   64
#define FFD  4096
#define MROWS (BZ * SQ)            // 4096

// ---------------------------------------------------------------------------
// Scratch (device globals; no allocations allowed). 112 MB total.
//   g_a: q   -> ctx (flash aliasing is safe) -> y2 (FF2 out)
//   g_b: k   -> y  (attn out + resid)
//   g_c: v   -> x1 (LN1 out, FF2 residual)
//   g_f: ffh
// ---------------------------------------------------------------------------
__device__ float g_a[(size_t)MROWS * DM];              // 16 MB
__device__ float g_b[(size_t)MROWS * DM];              // 16 MB
__device__ float g_c[(size_t)MROWS * DM];              // 16 MB
__device__ float g_f[(size_t)MROWS * FFD];             // 64 MB

// ---------------------------------------------------------------------------
// Helpers
// ---------------------------------------------------------------------------
__device__ __forceinline__ uint32_t smem_u32(const void* p) {
    return (uint32_t)__cvta_generic_to_shared(p);
}

#define LDMX4(r0, r1, r2, r3, addr)                                         \
    asm volatile("ldmatrix.sync.aligned.m8n8.x4.shared.b16 {%0,%1,%2,%3}, [%4];" \
                 : "=r"(r0), "=r"(r1), "=r"(r2), "=r"(r3) : "r"(addr))

#define MMA16816(d, a, b0, b1)                                              \
    asm volatile("mma.sync.aligned.m16n8k16.row.col.f32.f16.f16.f32 "        \
                 "{%0,%1,%2,%3}, {%4,%5,%6,%7}, {%8,%9}, {%0,%1,%2,%3};"     \
                 : "+f"(d[0]), "+f"(d[1]), "+f"(d[2]), "+f"(d[3])            \
                 : "r"(a[0]), "r"(a[1]), "r"(a[2]), "r"(a[3]),               \
                   "r"(b0), "r"(b1))

__device__ __forceinline__ float block_reduce_sum(float v) {
    __shared__ float sh[32];
    const unsigned mask = 0xffffffffu;
    #pragma unroll
    for (int o = 16; o > 0; o >>= 1) v += __shfl_xor_sync(mask, v, o);
    int lane = threadIdx.x & 31, w = threadIdx.x >> 5;
    __syncthreads();
    if (lane == 0) sh[w] = v;
    __syncthreads();
    int nw = (blockDim.x + 31) >> 5;
    if (w == 0) {
        v = (lane < nw) ? sh[lane] : 0.0f;
        #pragma unroll
        for (int o = 16; o > 0; o >>= 1) v += __shfl_xor_sync(mask, v, o);
        if (lane == 0) sh[0] = v;
    }
    __syncthreads();
    return sh[0];
}

// ---------------------------------------------------------------------------
// HMMA GEMM (TN): C = A @ B^T [+ bias] [+ resid], optional ReLU.
// A: [M,K] f32 row-major, B: [N,K] f32 row-major, C: [M,N] f32.
// fp32 -> fp16 conversion happens during the smem tile load; fp32 accumulate.
// Tile 128x128x64; 8 warps as 2(m) x 4(n); warp tile 64m x 32n.
// M, N, K must be multiples of 128/128/64 (true for all call sites).
// ---------------------------------------------------------------------------
template<bool RELU, bool RESID>
__global__ void __launch_bounds__(256, 2)
gemm_hmma(const float* __restrict__ A, int lda,
          const float* __restrict__ B, int ldb,
          const float* __restrict__ bias,
          const float* __restrict__ resid,
          float* __restrict__ C, int ldc,
          int M, int N, int K)
{
    constexpr int BK = 64;
    constexpr int LDS = BK + 8;           // 72 halves = 144B row stride
    __shared__ __align__(16) __half As[128][LDS];
    __shared__ __align__(16) __half Bs[128][LDS];

    const int tid  = threadIdx.x;
    const int warp = tid >> 5, lane = tid & 31;
    const int wm = warp >> 2;             // 0..1  (64-row slab)
    const int wn = warp & 3;              // 0..3  (32-col slab)
    const int row0 = blockIdx.y * 128;
    const int col0 = blockIdx.x * 128;

    float acc[4][4][4];
    #pragma unroll
    for (int mt = 0; mt < 4; mt++)
        #pragma unroll
        for (int nt = 0; nt < 4; nt++)
            #pragma unroll
            for (int r = 0; r < 4; r++) acc[mt][nt][r] = 0.0f;

    for (int k0 = 0; k0 < K; k0 += BK) {
        // ---- load + convert tiles (each thread: 8 float4 per tile)
        #pragma unroll
        for (int i = 0; i < 8; i++) {
            int linear = (i * 256 + tid) * 4;
            int r = linear >> 6, c = linear & 63;
            float4 t = *(const float4*)&A[(long)(row0 + r) * lda + k0 + c];
            __half2* dst = (__half2*)&As[r][c];
            dst[0] = __floats2half2_rn(t.x, t.y);
            dst[1] = __floats2half2_rn(t.z, t.w);
        }
        #pragma unroll
        for (int i = 0; i < 8; i++) {
            int linear = (i * 256 + tid) * 4;
            int r = linear >> 6, c = linear & 63;
            float4 t = *(const float4*)&B[(long)(col0 + r) * ldb + k0 + c];
            __half2* dst = (__half2*)&Bs[r][c];
            dst[0] = __floats2half2_rn(t.x, t.y);
            dst[1] = __floats2half2_rn(t.z, t.w);
        }
        __syncthreads();

        #pragma unroll
        for (int ks = 0; ks < 4; ks++) {
            const int kk = ks * 16;
            uint32_t a[4][4], br[2][4];
            #pragma unroll
            for (int mt = 0; mt < 4; mt++) {
                uint32_t addr = smem_u32(
                    &As[wm * 64 + mt * 16 + (lane & 15)][kk + (lane >> 4) * 8]);
                LDMX4(a[mt][0], a[mt][1], a[mt][2], a[mt][3], addr);
            }
            #pragma unroll
            for (int nt2 = 0; nt2 < 2; nt2++) {
                uint32_t addr = smem_u32(
                    &Bs[wn * 32 + nt2 * 16 + (lane & 15)][kk + (lane >> 4) * 8]);
                LDMX4(br[nt2][0], br[nt2][1], br[nt2][2], br[nt2][3], addr);
            }
            #pragma unroll
            for (int mt = 0; mt < 4; mt++)
                #pragma unroll
                for (int nt = 0; nt < 4; nt++) {
                    uint32_t b0 = br[nt >> 1][(nt & 1)];
                    uint32_t b1 = br[nt >> 1][(nt & 1) + 2];
                    MMA16816(acc[mt][nt], a[mt], b0, b1);
                }
        }
        __syncthreads();
    }

    // ---- epilogue: acc c0,c1 -> (row, col..col+1), c2,c3 -> (row+8)
    #pragma unroll
    for (int mt = 0; mt < 4; mt++) {
        int r0w = row0 + wm * 64 + mt * 16 + (lane >> 2);
        #pragma unroll
        for (int nt = 0; nt < 4; nt++) {
            int cn = col0 + wn * 32 + nt * 8 + 2 * (lane & 3);
            float v0 = acc[mt][nt][0], v1 = acc[mt][nt][1];
            float v2 = acc[mt][nt][2], v3 = acc[mt][nt][3];
            if (bias) {
                float b0v = bias[cn], b1v = bias[cn + 1];
                v0 += b0v; v1 += b1v; v2 += b0v; v3 += b1v;
            }
            if (RESID) {
                v0 += resid[(long)r0w * ldc + cn];
                v1 += resid[(long)r0w * ldc + cn + 1];
                v2 += resid[(long)(r0w + 8) * ldc + cn];
                v3 += resid[(long)(r0w + 8) * ldc + cn + 1];
            }
            if (RELU) {
                v0 = fmaxf(v0, 0.0f); v1 = fmaxf(v1, 0.0f);
                v2 = fmaxf(v2, 0.0f); v3 = fmaxf(v3, 0.0f);
            }
            *(float2*)&C[(long)r0w * ldc + cn]       = make_float2(v0, v1);
            *(float2*)&C[(long)(r0w + 8) * ldc + cn] = make_float2(v2, v3);
        }
    }
}

// ---------------------------------------------------------------------------
// Fused flash attention, fp32 (unchanged — known good).
// Q/K/V/O: [B*S, H*DH] row-major. 256 threads, BR=64, BC=64, online softmax.
// ---------------------------------------------------------------------------
#define SWZ(row, col) ((col) ^ ((row) & 31))

__global__ void __launch_bounds__(256)
flash_attn(const float* __restrict__ Q, const float* __restrict__ K,
           const float* __restrict__ V, float* __restrict__ O)
{
    __shared__ float Qs[64][64];
    __shared__ float KVs[64][64];
    __shared__ float Ps[64][64];

    const int bh = blockIdx.y;
    const int b  = bh / NH, h = bh % NH;
    const int q0 = blockIdx.x * 64;
    const long base = (long)b * SQ * DM + (long)h * DH;

    const int tid = threadIdx.x;
    const int tx  = tid % 16;
    const int ty  = tid / 16;

    #pragma unroll
    for (int idx = tid; idx < 64 * 64; idx += 256) {
        int r = idx >> 6, d = idx & 63;
        Qs[d][SWZ(d, r)] = Q[base + (long)(q0 + r) * DM + d];
    }

    float m[4], l[4], o[4][4];
    #pragma unroll
    for (int i = 0; i < 4; i++) {
        m[i] = -3.402823e38f; l[i] = 0.0f;
        #pragma unroll
        for (int j = 0; j < 4; j++) o[i][j] = 0.0f;
    }
    __syncthreads();

    for (int c0 = 0; c0 < SQ; c0 += 64) {
        #pragma unroll
        for (int idx = tid; idx < 64 * 64; idx += 256) {
            int c = idx >> 6, d = idx & 63;
            KVs[d][SWZ(d, c)] = K[base + (long)(c0 + c) * DM + d];
        }
        __syncthreads();

        float s[4][4];
        #pragma unroll
        for (int i = 0; i < 4; i++)
            #pragma unroll
            for (int j = 0; j < 4; j++) s[i][j] = 0.0f;

        #pragma unroll
        for (int d = 0; d < 64; d++) {
            float a[4], bb[4];
            #pragma unroll
            for (int i = 0; i < 4; i++) a[i]  = Qs[d][SWZ(d, ty * 4 + i)];
            #pragma unroll
            for (int j = 0; j < 4; j++) bb[j] = KVs[d][SWZ(d, tx * 4 + j)];
            #pragma unroll
            for (int i = 0; i < 4; i++)
                #pragma unroll
                for (int j = 0; j < 4; j++)
                    s[i][j] = fmaf(a[i], bb[j], s[i][j]);
        }

        #pragma unroll
        for (int i = 0; i < 4; i++) {
            float mt = fmaxf(fmaxf(s[i][0], s[i][1]), fmaxf(s[i][2], s[i][3])) * 0.125f;
            #pragma unroll
            for (int off = 8; off > 0; off >>= 1)
                mt = fmaxf(mt, __shfl_xor_sync(0xffffffffu, mt, off, 16));
            float mnew = fmaxf(m[i], mt);
            float corr = __expf(m[i] - mnew);
            float rs = 0.0f;
            #pragma unroll
            for (int j = 0; j < 4; j++) {
                float p = __expf(s[i][j] * 0.125f - mnew);
                Ps[tx * 4 + j][SWZ(tx * 4 + j, ty * 4 + i)] = p;
                rs += p;
            }
            #pragma unroll
            for (int off = 8; off > 0; off >>= 1)
                rs += __shfl_xor_sync(0xffffffffu, rs, off, 16);
            l[i] = l[i] * corr + rs;
            m[i] = mnew;
            #pragma unroll
            for (int j = 0; j < 4; j++) o[i][j] *= corr;
        }
        __syncthreads();

        #pragma unroll
        for (int idx = tid; idx < 64 * 64; idx += 256) {
            int c = idx >> 6, d = idx & 63;
            KVs[c][d] = V[base + (long)(c0 + c) * DM + d];
        }
        __syncthreads();

        #pragma unroll
        for (int c = 0; c < 64; c++) {
            float a[4], bb[4];
            #pragma unroll
            for (int i = 0; i < 4; i++) a[i]  = Ps[c][SWZ(c, ty * 4 + i)];
            #pragma unroll
            for (int j = 0; j < 4; j++) bb[j] = KVs[c][tx * 4 + j];
            #pragma unroll
            for (int i = 0; i < 4; i++)
                #pragma unroll
                for (int j = 0; j < 4; j++)
                    o[i][j] = fmaf(a[i], bb[j], o[i][j]);
        }
        __syncthreads();
    }

    #pragma unroll
    for (int i = 0; i < 4; i++) {
        const float inv = 1.0f / l[i];
        #pragma unroll
        for (int j = 0; j < 4; j++)
            O[base + (long)(q0 + ty * 4 + i) * DM + (tx * 4 + j)] = o[i][j] * inv;
    }
}

// ---------------------------------------------------------------------------
// LayerNorm over rows of length 1024
// ---------------------------------------------------------------------------
__global__ void __launch_bounds__(256)
layernorm1024(const float* __restrict__ x, const float* __restrict__ g,
              const float* __restrict__ b, float* __restrict__ out)
{
    const long row = blockIdx.x;
    const float* p = x + row * (long)DM;
    float v[4];
    float s = 0.0f;
    #pragma unroll
    for (int i = 0; i < 4; i++) {
        v[i] = p[threadIdx.x + i * 256];
        s += v[i];
    }
    s = block_reduce_sum(s);
    const float mean = s * (1.0f / DM);
    float s2 = 0.0f;
    #pragma unroll
    for (int i = 0; i < 4; i++) {
        float d = v[i] - mean;
        s2 += d * d;
    }
    s2 = block_reduce_sum(s2);
    const float rstd = rsqrtf(s2 * (1.0f / DM) + 1e-5f);
    #pragma unroll
    for (int i = 0; i < 4; i++) {
        int c = threadIdx.x + i * 256;
        out[row * (long)DM + c] = (v[i] - mean) * rstd * g[c] + b[c];
    }
}

// ---------------------------------------------------------------------------
// Launch orchestration (graph-capturable: kernel launches only)
// ---------------------------------------------------------------------------
extern "C" void kernel_launch(void* const* d_in, const int* in_sizes, int n_in,
                              void* d_out, int out_size)
{
    const float* src   = (const float*)d_in[0];
    const float* qw    = (const float*)d_in[1];
    const float* qb    = (const float*)d_in[2];
    const float* kw    = (const float*)d_in[3];
    const float* kb    = (const float*)d_in[4];
    const float* vw    = (const float*)d_in[5];
    const float* vb    = (const float*)d_in[6];
    const float* ow    = (const float*)d_in[7];
    const float* ob    = (const float*)d_in[8];
    const float* w1    = (const float*)d_in[9];
    const float* b1    = (const float*)d_in[10];
    const float* w2    = (const float*)d_in[11];
    const float* b2    = (const float*)d_in[12];
    const float* g1    = (const float*)d_in[13];
    const float* beta1 = (const float*)d_in[14];
    const float* g2    = (const float*)d_in[15];
    const float* beta2 = (const float*)d_in[16];
    float* out = (float*)d_out;

    float *ga, *gb, *gc, *gf;
    cudaGetSymbolAddress((void**)&ga, g_a);
    cudaGetSymbolAddress((void**)&gb, g_b);
    cudaGetSymbolAddress((void**)&gc, g_c);
    cudaGetSymbolAddress((void**)&gf, g_f);

    const dim3 blk(256);

    // ---- QKV projections: q->ga, k->gb, v->gc
    {
        dim3 g(DM / 128, MROWS / 128);
        gemm_hmma<false,false><<<g, blk>>>(
            src, DM, qw, DM, qb, nullptr, ga, DM, MROWS, DM, DM);
        gemm_hmma<false,false><<<g, blk>>>(
            src, DM, kw, DM, kb, nullptr, gb, DM, MROWS, DM, DM);
        gemm_hmma<false,false><<<g, blk>>>(
            src, DM, vw, DM, vb, nullptr, gc, DM, MROWS, DM, DM);
    }

    // ---- fused attention: ctx = softmax(QK^T/8) V  (ctx aliases q in ga)
    {
        dim3 g(SQ / 64, BZ * NH);
        flash_attn<<<g, blk>>>(ga, gb, gc, ga);
    }

    // ---- O projection + residual: y(gb) = ctx(ga) @ ow^T + ob + src
    {
        dim3 g(DM / 128, MROWS / 128);
        gemm_hmma<false,true><<<g, blk>>>(
            ga, DM, ow, DM, ob, src, gb, DM, MROWS, DM, DM);
    }

    // ---- LN1: x1(gc) = LN(y)
    layernorm1024<<<MROWS, blk>>>(gb, g1, beta1, gc);

    // ---- FF1: ffh(gf) = relu(x1 @ w1^T + b1)
    {
        dim3 g(FFD / 128, MROWS / 128);
        gemm_hmma<true,false><<<g, blk>>>(
            gc, DM, w1, DM, b1, nullptr, gf, FFD, MROWS, FFD, DM);
    }

    // ---- FF2 + residual: y2(ga) = ffh @ w2^T + b2 + x1(gc)
    {
        dim3 g(DM / 128, MROWS / 128);
        gemm_hmma<false,true><<<g, blk>>>(
            gf, FFD, w2, FFD, b2, gc, ga, DM, MROWS, DM, FFD);
    }

    // ---- LN2 -> output
    layernorm1024<<<MROWS, blk>>>(ga, g2, beta2, out);
}

// round 8
// speedup vs baseline: 5.0325x; 2.6223x over previous
#include <cuda_runtime.h>
#include <cuda_fp16.h>
#include <cstdint>

// ---------------------------------------------------------------------------
// Problem constants
// ---------------------------------------------------------------------------
#define BZ   2
#define SQ   2048
#define DM   1024
#define NH   16
#define DH   64
#define FFD  4096
#define MROWS (BZ * SQ)            // 4096

// ---------------------------------------------------------------------------
// Scratch (device globals). 112 MB total.
//   g_a: q -> ctx (flash alias safe) -> y2 ; g_b: k -> y ; g_c: v -> x1 ; g_f: ffh
// ---------------------------------------------------------------------------
__device__ float g_a[(size_t)MROWS * DM];
__device__ float g_b[(size_t)MROWS * DM];
__device__ float g_c[(size_t)MROWS * DM];
__device__ float g_f[(size_t)MROWS * FFD];

// ---------------------------------------------------------------------------
// Helpers
// ---------------------------------------------------------------------------
__device__ __forceinline__ uint32_t smem_u32(const void* p) {
    return (uint32_t)__cvta_generic_to_shared(p);
}

#define LDMX4(r0, r1, r2, r3, addr)                                         \
    asm volatile("ldmatrix.sync.aligned.m8n8.x4.shared.b16 {%0,%1,%2,%3}, [%4];" \
                 : "=r"(r0), "=r"(r1), "=r"(r2), "=r"(r3) : "r"(addr))

#define MMA16816(d, a, b0, b1)                                              \
    asm volatile("mma.sync.aligned.m16n8k16.row.col.f32.f16.f16.f32 "        \
                 "{%0,%1,%2,%3}, {%4,%5,%6,%7}, {%8,%9}, {%0,%1,%2,%3};"     \
                 : "+f"(d[0]), "+f"(d[1]), "+f"(d[2]), "+f"(d[3])            \
                 : "r"(a[0]), "r"(a[1]), "r"(a[2]), "r"(a[3]),               \
                   "r"(b0), "r"(b1))

__device__ __forceinline__ float block_reduce_sum(float v) {
    __shared__ float sh[32];
    const unsigned mask = 0xffffffffu;
    #pragma unroll
    for (int o = 16; o > 0; o >>= 1) v += __shfl_xor_sync(mask, v, o);
    int lane = threadIdx.x & 31, w = threadIdx.x >> 5;
    __syncthreads();
    if (lane == 0) sh[w] = v;
    __syncthreads();
    int nw = (blockDim.x + 31) >> 5;
    if (w == 0) {
        v = (lane < nw) ? sh[lane] : 0.0f;
        #pragma unroll
        for (int o = 16; o > 0; o >>= 1) v += __shfl_xor_sync(mask, v, o);
        if (lane == 0) sh[0] = v;
    }
    __syncthreads();
    return sh[0];
}

// ---------------------------------------------------------------------------
// HMMA GEMM (TN): unchanged (proven at R4/R5).
// ---------------------------------------------------------------------------
template<bool RELU, bool RESID>
__global__ void __launch_bounds__(256, 2)
gemm_hmma(const float* __restrict__ A, int lda,
          const float* __restrict__ B, int ldb,
          const float* __restrict__ bias,
          const float* __restrict__ resid,
          float* __restrict__ C, int ldc,
          int M, int N, int K)
{
    constexpr int BK = 64;
    constexpr int LDS = BK + 8;
    __shared__ __align__(16) __half As[128][LDS];
    __shared__ __align__(16) __half Bs[128][LDS];

    const int tid  = threadIdx.x;
    const int warp = tid >> 5, lane = tid & 31;
    const int wm = warp >> 2;
    const int wn = warp & 3;
    const int row0 = blockIdx.y * 128;
    const int col0 = blockIdx.x * 128;

    float acc[4][4][4];
    #pragma unroll
    for (int mt = 0; mt < 4; mt++)
        #pragma unroll
        for (int nt = 0; nt < 4; nt++)
            #pragma unroll
            for (int r = 0; r < 4; r++) acc[mt][nt][r] = 0.0f;

    for (int k0 = 0; k0 < K; k0 += BK) {
        #pragma unroll
        for (int i = 0; i < 8; i++) {
            int linear = (i * 256 + tid) * 4;
            int r = linear >> 6, c = linear & 63;
            float4 t = *(const float4*)&A[(long)(row0 + r) * lda + k0 + c];
            __half2* dst = (__half2*)&As[r][c];
            dst[0] = __floats2half2_rn(t.x, t.y);
            dst[1] = __floats2half2_rn(t.z, t.w);
        }
        #pragma unroll
        for (int i = 0; i < 8; i++) {
            int linear = (i * 256 + tid) * 4;
            int r = linear >> 6, c = linear & 63;
            float4 t = *(const float4*)&B[(long)(col0 + r) * ldb + k0 + c];
            __half2* dst = (__half2*)&Bs[r][c];
            dst[0] = __floats2half2_rn(t.x, t.y);
            dst[1] = __floats2half2_rn(t.z, t.w);
        }
        __syncthreads();

        #pragma unroll
        for (int ks = 0; ks < 4; ks++) {
            const int kk = ks * 16;
            uint32_t a[4][4], br[2][4];
            #pragma unroll
            for (int mt = 0; mt < 4; mt++) {
                uint32_t addr = smem_u32(
                    &As[wm * 64 + mt * 16 + (lane & 15)][kk + (lane >> 4) * 8]);
                LDMX4(a[mt][0], a[mt][1], a[mt][2], a[mt][3], addr);
            }
            #pragma unroll
            for (int nt2 = 0; nt2 < 2; nt2++) {
                uint32_t addr = smem_u32(
                    &Bs[wn * 32 + nt2 * 16 + (lane & 15)][kk + (lane >> 4) * 8]);
                LDMX4(br[nt2][0], br[nt2][1], br[nt2][2], br[nt2][3], addr);
            }
            #pragma unroll
            for (int mt = 0; mt < 4; mt++)
                #pragma unroll
                for (int nt = 0; nt < 4; nt++) {
                    uint32_t b0 = br[nt >> 1][(nt & 1)];
                    uint32_t b1 = br[nt >> 1][(nt & 1) + 2];
                    MMA16816(acc[mt][nt], a[mt], b0, b1);
                }
        }
        __syncthreads();
    }

    #pragma unroll
    for (int mt = 0; mt < 4; mt++) {
        int r0w = row0 + wm * 64 + mt * 16 + (lane >> 2);
        #pragma unroll
        for (int nt = 0; nt < 4; nt++) {
            int cn = col0 + wn * 32 + nt * 8 + 2 * (lane & 3);
            float v0 = acc[mt][nt][0], v1 = acc[mt][nt][1];
            float v2 = acc[mt][nt][2], v3 = acc[mt][nt][3];
            if (bias) {
                float b0v = bias[cn], b1v = bias[cn + 1];
                v0 += b0v; v1 += b1v; v2 += b0v; v3 += b1v;
            }
            if (RESID) {
                v0 += resid[(long)r0w * ldc + cn];
                v1 += resid[(long)r0w * ldc + cn + 1];
                v2 += resid[(long)(r0w + 8) * ldc + cn];
                v3 += resid[(long)(r0w + 8) * ldc + cn + 1];
            }
            if (RELU) {
                v0 = fmaxf(v0, 0.0f); v1 = fmaxf(v1, 0.0f);
                v2 = fmaxf(v2, 0.0f); v3 = fmaxf(v3, 0.0f);
            }
            *(float2*)&C[(long)r0w * ldc + cn]       = make_float2(v0, v1);
            *(float2*)&C[(long)(r0w + 8) * ldc + cn] = make_float2(v2, v3);
        }
    }
}

// ---------------------------------------------------------------------------
// Flash attention on HMMA tensor cores.
// Q/K/V/O: [B*S, H*DH] f32 row-major. Block: 256 thr (8 warps), BR=128 query
// rows (16/warp), BC=64 keys/iter, online softmax in mma register layout,
// P kept in registers (S-acc -> A-frag identity mapping). V stored transposed
// + XOR-swizzled in smem for the PV B-fragments. O may alias Q (block reads
// its own Q rows to smem up front, writes only those rows at the end).
// ---------------------------------------------------------------------------
__global__ void __launch_bounds__(256)
flash_hmma(const float* __restrict__ Q, const float* __restrict__ K,
           const float* __restrict__ V, float* __restrict__ O)
{
    __shared__ __align__(16) __half Qs[128][72];
    __shared__ __align__(16) __half Ks[64][72];
    __shared__ __align__(16) __half Vs[64][72];   // [dh][key^((dh&7)<<3)]

    const int bh = blockIdx.y;
    const int b  = bh / NH, h = bh % NH;
    const int q0 = blockIdx.x * 128;
    const long base = (long)b * SQ * DM + (long)h * DH;

    const int tid  = threadIdx.x;
    const int warp = tid >> 5, lane = tid & 31;

    // ---- Q tile f32 -> fp16 smem (128 rows x 64)
    #pragma unroll
    for (int i = 0; i < 8; i++) {
        int linear = i * 256 + tid;
        int r = linear >> 4, dq = (linear & 15) * 4;
        float4 t = *(const float4*)&Q[base + (long)(q0 + r) * DM + dq];
        __half2* dst = (__half2*)&Qs[r][dq];
        dst[0] = __floats2half2_rn(t.x, t.y);
        dst[1] = __floats2half2_rn(t.z, t.w);
    }
    __syncthreads();

    // ---- Q fragments once into registers: warp rows 16w..16w+15
    uint32_t qf[4][4];
    #pragma unroll
    for (int kc = 0; kc < 4; kc++) {
        uint32_t addr = smem_u32(
            &Qs[warp * 16 + (lane & 15)][kc * 16 + (lane >> 4) * 8]);
        LDMX4(qf[kc][0], qf[kc][1], qf[kc][2], qf[kc][3], addr);
    }

    float o[8][4];
    #pragma unroll
    for (int nt = 0; nt < 8; nt++)
        #pragma unroll
        for (int r = 0; r < 4; r++) o[nt][r] = 0.0f;
    float m_lo = -3.0e38f, m_hi = -3.0e38f, l_lo = 0.0f, l_hi = 0.0f;

    for (int c0 = 0; c0 < SQ; c0 += 64) {
        __syncthreads();   // previous iteration's Ks/Vs fully consumed
        // ---- K tile natural [key][dh]
        #pragma unroll
        for (int i = 0; i < 4; i++) {
            int linear = i * 256 + tid;
            int c = linear >> 4, dq = (linear & 15) * 4;
            float4 t = *(const float4*)&K[base + (long)(c0 + c) * DM + dq];
            __half2* dst = (__half2*)&Ks[c][dq];
            dst[0] = __floats2half2_rn(t.x, t.y);
            dst[1] = __floats2half2_rn(t.z, t.w);
        }
        // ---- V tile transposed + swizzled [dh][key]
        #pragma unroll
        for (int i = 0; i < 4; i++) {
            int linear = i * 256 + tid;
            int c = linear >> 4, dq = (linear & 15) * 4;
            float4 t = *(const float4*)&V[base + (long)(c0 + c) * DM + dq];
            Vs[dq + 0][c ^ (((dq + 0) & 7) << 3)] = __float2half(t.x);
            Vs[dq + 1][c ^ (((dq + 1) & 7) << 3)] = __float2half(t.y);
            Vs[dq + 2][c ^ (((dq + 2) & 7) << 3)] = __float2half(t.z);
            Vs[dq + 3][c ^ (((dq + 3) & 7) << 3)] = __float2half(t.w);
        }
        __syncthreads();

        // ---- S = Q @ K^T : s[nt] covers keys 8*nt..8*nt+7
        float s[8][4];
        #pragma unroll
        for (int nt = 0; nt < 8; nt++)
            #pragma unroll
            for (int r = 0; r < 4; r++) s[nt][r] = 0.0f;

        #pragma unroll
        for (int kc = 0; kc < 4; kc++) {
            uint32_t br[4][4];
            #pragma unroll
            for (int nt2 = 0; nt2 < 4; nt2++) {
                uint32_t addr = smem_u32(
                    &Ks[nt2 * 16 + (lane & 15)][kc * 16 + (lane >> 4) * 8]);
                LDMX4(br[nt2][0], br[nt2][1], br[nt2][2], br[nt2][3], addr);
            }
            #pragma unroll
            for (int nt = 0; nt < 8; nt++)
                MMA16816(s[nt], qf[kc],
                         br[nt >> 1][nt & 1], br[nt >> 1][(nt & 1) + 2]);
        }

        // ---- online softmax (logit = s * 0.125)
        float mt_lo = -3.0e38f, mt_hi = -3.0e38f;
        #pragma unroll
        for (int nt = 0; nt < 8; nt++) {
            mt_lo = fmaxf(mt_lo, fmaxf(s[nt][0], s[nt][1]));
            mt_hi = fmaxf(mt_hi, fmaxf(s[nt][2], s[nt][3]));
        }
        mt_lo *= 0.125f; mt_hi *= 0.125f;
        mt_lo = fmaxf(mt_lo, __shfl_xor_sync(0xffffffffu, mt_lo, 1));
        mt_lo = fmaxf(mt_lo, __shfl_xor_sync(0xffffffffu, mt_lo, 2));
        mt_hi = fmaxf(mt_hi, __shfl_xor_sync(0xffffffffu, mt_hi, 1));
        mt_hi = fmaxf(mt_hi, __shfl_xor_sync(0xffffffffu, mt_hi, 2));

        const float mn_lo = fmaxf(m_lo, mt_lo), mn_hi = fmaxf(m_hi, mt_hi);
        const float corr_lo = __expf(m_lo - mn_lo);
        const float corr_hi = __expf(m_hi - mn_hi);
        m_lo = mn_lo; m_hi = mn_hi;

        uint32_t pp[8][2];
        float rs_lo = 0.0f, rs_hi = 0.0f;
        #pragma unroll
        for (int nt = 0; nt < 8; nt++) {
            float p0 = __expf(fmaf(s[nt][0], 0.125f, -mn_lo));
            float p1 = __expf(fmaf(s[nt][1], 0.125f, -mn_lo));
            float p2 = __expf(fmaf(s[nt][2], 0.125f, -mn_hi));
            float p3 = __expf(fmaf(s[nt][3], 0.125f, -mn_hi));
            rs_lo += p0 + p1; rs_hi += p2 + p3;
            __half2 h01 = __floats2half2_rn(p0, p1);
            __half2 h23 = __floats2half2_rn(p2, p3);
            pp[nt][0] = *(uint32_t*)&h01;
            pp[nt][1] = *(uint32_t*)&h23;
        }
        rs_lo += __shfl_xor_sync(0xffffffffu, rs_lo, 1);
        rs_lo += __shfl_xor_sync(0xffffffffu, rs_lo, 2);
        rs_hi += __shfl_xor_sync(0xffffffffu, rs_hi, 1);
        rs_hi += __shfl_xor_sync(0xffffffffu, rs_hi, 2);
        l_lo = l_lo * corr_lo + rs_lo;
        l_hi = l_hi * corr_hi + rs_hi;
        #pragma unroll
        for (int nt = 0; nt < 8; nt++) {
            o[nt][0] *= corr_lo; o[nt][1] *= corr_lo;
            o[nt][2] *= corr_hi; o[nt][3] *= corr_hi;
        }

        // ---- O += P @ V  (A-frag = pp, B-frag from transposed/swizzled Vs)
        #pragma unroll
        for (int kc = 0; kc < 4; kc++) {
            uint32_t a[4] = { pp[2 * kc][0], pp[2 * kc][1],
                              pp[2 * kc + 1][0], pp[2 * kc + 1][1] };
            uint32_t br[4][4];
            #pragma unroll
            for (int nt2 = 0; nt2 < 4; nt2++) {
                int row = nt2 * 16 + (lane & 15);
                uint32_t addr = smem_u32(
                    &Vs[row][(kc * 16 + (lane >> 4) * 8) ^ ((row & 7) << 3)]);
                LDMX4(br[nt2][0], br[nt2][1], br[nt2][2], br[nt2][3], addr);
            }
            #pragma unroll
            for (int nt = 0; nt < 8; nt++)
                MMA16816(o[nt], a,
                         br[nt >> 1][nt & 1], br[nt >> 1][(nt & 1) + 2]);
        }
    }

    // ---- epilogue
    const float inv_lo = 1.0f / l_lo, inv_hi = 1.0f / l_hi;
    const long row_lo = q0 + warp * 16 + (lane >> 2);
    #pragma unroll
    for (int nt = 0; nt < 8; nt++) {
        int col = nt * 8 + 2 * (lane & 3);
        *(float2*)&O[base + row_lo * DM + col] =
            make_float2(o[nt][0] * inv_lo, o[nt][1] * inv_lo);
        *(float2*)&O[base + (row_lo + 8) * DM + col] =
            make_float2(o[nt][2] * inv_hi, o[nt][3] * inv_hi);
    }
}

// ---------------------------------------------------------------------------
// LayerNorm over rows of length 1024
// ---------------------------------------------------------------------------
__global__ void __launch_bounds__(256)
layernorm1024(const float* __restrict__ x, const float* __restrict__ g,
              const float* __restrict__ b, float* __restrict__ out)
{
    const long row = blockIdx.x;
    const float* p = x + row * (long)DM;
    float v[4];
    float s = 0.0f;
    #pragma unroll
    for (int i = 0; i < 4; i++) {
        v[i] = p[threadIdx.x + i * 256];
        s += v[i];
    }
    s = block_reduce_sum(s);
    const float mean = s * (1.0f / DM);
    float s2 = 0.0f;
    #pragma unroll
    for (int i = 0; i < 4; i++) {
        float d = v[i] - mean;
        s2 += d * d;
    }
    s2 = block_reduce_sum(s2);
    const float rstd = rsqrtf(s2 * (1.0f / DM) + 1e-5f);
    #pragma unroll
    for (int i = 0; i < 4; i++) {
        int c = threadIdx.x + i * 256;
        out[row * (long)DM + c] = (v[i] - mean) * rstd * g[c] + b[c];
    }
}

// ---------------------------------------------------------------------------
// Launch orchestration (graph-capturable: kernel launches only)
// ---------------------------------------------------------------------------
extern "C" void kernel_launch(void* const* d_in, const int* in_sizes, int n_in,
                              void* d_out, int out_size)
{
    const float* src   = (const float*)d_in[0];
    const float* qw    = (const float*)d_in[1];
    const float* qb    = (const float*)d_in[2];
    const float* kw    = (const float*)d_in[3];
    const float* kb    = (const float*)d_in[4];
    const float* vw    = (const float*)d_in[5];
    const float* vb    = (const float*)d_in[6];
    const float* ow    = (const float*)d_in[7];
    const float* ob    = (const float*)d_in[8];
    const float* w1    = (const float*)d_in[9];
    const float* b1    = (const float*)d_in[10];
    const float* w2    = (const float*)d_in[11];
    const float* b2    = (const float*)d_in[12];
    const float* g1    = (const float*)d_in[13];
    const float* beta1 = (const float*)d_in[14];
    const float* g2    = (const float*)d_in[15];
    const float* beta2 = (const float*)d_in[16];
    float* out = (float*)d_out;

    float *ga, *gb, *gc, *gf;
    cudaGetSymbolAddress((void**)&ga, g_a);
    cudaGetSymbolAddress((void**)&gb, g_b);
    cudaGetSymbolAddress((void**)&gc, g_c);
    cudaGetSymbolAddress((void**)&gf, g_f);

    const dim3 blk(256);

    // ---- QKV projections
    {
        dim3 g(DM / 128, MROWS / 128);
        gemm_hmma<false,false><<<g, blk>>>(
            src, DM, qw, DM, qb, nullptr, ga, DM, MROWS, DM, DM);
        gemm_hmma<false,false><<<g, blk>>>(
            src, DM, kw, DM, kb, nullptr, gb, DM, MROWS, DM, DM);
        gemm_hmma<false,false><<<g, blk>>>(
            src, DM, vw, DM, vb, nullptr, gc, DM, MROWS, DM, DM);
    }

    // ---- fused attention (tensor cores); ctx aliases q in ga
    {
        dim3 g(SQ / 128, BZ * NH);
        flash_hmma<<<g, blk>>>(ga, gb, gc, ga);
    }

    // ---- O projection + residual
    {
        dim3 g(DM / 128, MROWS / 128);
        gemm_hmma<false,true><<<g, blk>>>(
            ga, DM, ow, DM, ob, src, gb, DM, MROWS, DM, DM);
    }

    // ---- LN1
    layernorm1024<<<MROWS, blk>>>(gb, g1, beta1, gc);

    // ---- FF1
    {
        dim3 g(FFD / 128, MROWS / 128);
        gemm_hmma<true,false><<<g, blk>>>(
            gc, DM, w1, DM, b1, nullptr, gf, FFD, MROWS, FFD, DM);
    }

    // ---- FF2 + residual
    {
        dim3 g(DM / 128, MROWS / 128);
        gemm_hmma<false,true><<<g, blk>>>(
            gf, FFD, w2, FFD, b2, gc, ga, DM, MROWS, DM, FFD);
    }

    // ---- LN2 -> output
    layernorm1024<<<MROWS, blk>>>(ga, g2, beta2, out);
}

// round 9
// speedup vs baseline: 5.3854x; 1.0701x over previous
#include <cuda_runtime.h>
#include <cuda_fp16.h>
#include <cstdint>

// ---------------------------------------------------------------------------
// Problem constants
// ---------------------------------------------------------------------------
#define BZ   2
#define SQ   2048
#define DM   1024
#define NH   16
#define DH   64
#define FFD  4096
#define MROWS (BZ * SQ)            // 4096

// ---------------------------------------------------------------------------
// Scratch (device globals). 112 MB total.
//   g_a: q -> ctx (flash alias safe) -> y2 ; g_b: k -> y ; g_c: v -> x1 ; g_f: ffh
// ---------------------------------------------------------------------------
__device__ float g_a[(size_t)MROWS * DM];
__device__ float g_b[(size_t)MROWS * DM];
__device__ float g_c[(size_t)MROWS * DM];
__device__ float g_f[(size_t)MROWS * FFD];

// ---------------------------------------------------------------------------
// Helpers
// ---------------------------------------------------------------------------
__device__ __forceinline__ uint32_t smem_u32(const void* p) {
    return (uint32_t)__cvta_generic_to_shared(p);
}

#define LDMX4(r0, r1, r2, r3, addr)                                         \
    asm volatile("ldmatrix.sync.aligned.m8n8.x4.shared.b16 {%0,%1,%2,%3}, [%4];" \
                 : "=r"(r0), "=r"(r1), "=r"(r2), "=r"(r3) : "r"(addr))

#define MMA16816(d, a, b0, b1)                                              \
    asm volatile("mma.sync.aligned.m16n8k16.row.col.f32.f16.f16.f32 "        \
                 "{%0,%1,%2,%3}, {%4,%5,%6,%7}, {%8,%9}, {%0,%1,%2,%3};"     \
                 : "+f"(d[0]), "+f"(d[1]), "+f"(d[2]), "+f"(d[3])            \
                 : "r"(a[0]), "r"(a[1]), "r"(a[2]), "r"(a[3]),               \
                   "r"(b0), "r"(b1))

__device__ __forceinline__ float block_reduce_sum(float v) {
    __shared__ float sh[32];
    const unsigned mask = 0xffffffffu;
    #pragma unroll
    for (int o = 16; o > 0; o >>= 1) v += __shfl_xor_sync(mask, v, o);
    int lane = threadIdx.x & 31, w = threadIdx.x >> 5;
    __syncthreads();
    if (lane == 0) sh[w] = v;
    __syncthreads();
    int nw = (blockDim.x + 31) >> 5;
    if (w == 0) {
        v = (lane < nw) ? sh[lane] : 0.0f;
        #pragma unroll
        for (int o = 16; o > 0; o >>= 1) v += __shfl_xor_sync(mask, v, o);
        if (lane == 0) sh[0] = v;
    }
    __syncthreads();
    return sh[0];
}

// ---------------------------------------------------------------------------
// HMMA GEMM (TN): unchanged (proven at R4/R5/R8).
// ---------------------------------------------------------------------------
template<bool RELU, bool RESID>
__global__ void __launch_bounds__(256, 2)
gemm_hmma(const float* __restrict__ A, int lda,
          const float* __restrict__ B, int ldb,
          const float* __restrict__ bias,
          const float* __restrict__ resid,
          float* __restrict__ C, int ldc,
          int M, int N, int K)
{
    constexpr int BK = 64;
    constexpr int LDS = BK + 8;
    __shared__ __align__(16) __half As[128][LDS];
    __shared__ __align__(16) __half Bs[128][LDS];

    const int tid  = threadIdx.x;
    const int warp = tid >> 5, lane = tid & 31;
    const int wm = warp >> 2;
    const int wn = warp & 3;
    const int row0 = blockIdx.y * 128;
    const int col0 = blockIdx.x * 128;

    float acc[4][4][4];
    #pragma unroll
    for (int mt = 0; mt < 4; mt++)
        #pragma unroll
        for (int nt = 0; nt < 4; nt++)
            #pragma unroll
            for (int r = 0; r < 4; r++) acc[mt][nt][r] = 0.0f;

    for (int k0 = 0; k0 < K; k0 += BK) {
        #pragma unroll
        for (int i = 0; i < 8; i++) {
            int linear = (i * 256 + tid) * 4;
            int r = linear >> 6, c = linear & 63;
            float4 t = *(const float4*)&A[(long)(row0 + r) * lda + k0 + c];
            __half2* dst = (__half2*)&As[r][c];
            dst[0] = __floats2half2_rn(t.x, t.y);
            dst[1] = __floats2half2_rn(t.z, t.w);
        }
        #pragma unroll
        for (int i = 0; i < 8; i++) {
            int linear = (i * 256 + tid) * 4;
            int r = linear >> 6, c = linear & 63;
            float4 t = *(const float4*)&B[(long)(col0 + r) * ldb + k0 + c];
            __half2* dst = (__half2*)&Bs[r][c];
            dst[0] = __floats2half2_rn(t.x, t.y);
            dst[1] = __floats2half2_rn(t.z, t.w);
        }
        __syncthreads();

        #pragma unroll
        for (int ks = 0; ks < 4; ks++) {
            const int kk = ks * 16;
            uint32_t a[4][4], br[2][4];
            #pragma unroll
            for (int mt = 0; mt < 4; mt++) {
                uint32_t addr = smem_u32(
                    &As[wm * 64 + mt * 16 + (lane & 15)][kk + (lane >> 4) * 8]);
                LDMX4(a[mt][0], a[mt][1], a[mt][2], a[mt][3], addr);
            }
            #pragma unroll
            for (int nt2 = 0; nt2 < 2; nt2++) {
                uint32_t addr = smem_u32(
                    &Bs[wn * 32 + nt2 * 16 + (lane & 15)][kk + (lane >> 4) * 8]);
                LDMX4(br[nt2][0], br[nt2][1], br[nt2][2], br[nt2][3], addr);
            }
            #pragma unroll
            for (int mt = 0; mt < 4; mt++)
                #pragma unroll
                for (int nt = 0; nt < 4; nt++) {
                    uint32_t b0 = br[nt >> 1][(nt & 1)];
                    uint32_t b1 = br[nt >> 1][(nt & 1) + 2];
                    MMA16816(acc[mt][nt], a[mt], b0, b1);
                }
        }
        __syncthreads();
    }

    #pragma unroll
    for (int mt = 0; mt < 4; mt++) {
        int r0w = row0 + wm * 64 + mt * 16 + (lane >> 2);
        #pragma unroll
        for (int nt = 0; nt < 4; nt++) {
            int cn = col0 + wn * 32 + nt * 8 + 2 * (lane & 3);
            float v0 = acc[mt][nt][0], v1 = acc[mt][nt][1];
            float v2 = acc[mt][nt][2], v3 = acc[mt][nt][3];
            if (bias) {
                float b0v = bias[cn], b1v = bias[cn + 1];
                v0 += b0v; v1 += b1v; v2 += b0v; v3 += b1v;
            }
            if (RESID) {
                v0 += resid[(long)r0w * ldc + cn];
                v1 += resid[(long)r0w * ldc + cn + 1];
                v2 += resid[(long)(r0w + 8) * ldc + cn];
                v3 += resid[(long)(r0w + 8) * ldc + cn + 1];
            }
            if (RELU) {
                v0 = fmaxf(v0, 0.0f); v1 = fmaxf(v1, 0.0f);
                v2 = fmaxf(v2, 0.0f); v3 = fmaxf(v3, 0.0f);
            }
            *(float2*)&C[(long)r0w * ldc + cn]       = make_float2(v0, v1);
            *(float2*)&C[(long)(r0w + 8) * ldc + cn] = make_float2(v2, v3);
        }
    }
}

// ---------------------------------------------------------------------------
// Flash attention on HMMA, v2: 4 warps x 32 query rows (BR=128, BC=64).
// K/V fragments loaded once per kc and reused across both 16-row tiles,
// halving smem fragment traffic vs the 8-warp version. Q smem is unioned
// with K/V smem (Q lives in registers before the KV loop starts).
// O may alias Q (block reads its own Q rows up front, writes them at end).
// ---------------------------------------------------------------------------
__global__ void __launch_bounds__(128)
flash_hmma(const float* __restrict__ Q, const float* __restrict__ K,
           const float* __restrict__ V, float* __restrict__ O)
{
    __shared__ __align__(16) union SmemU {
        __half q[128][72];                        // 18432 B (Q phase)
        struct { __half k[64][72]; __half v[64][72]; } kv;  // KV phase
    } sm;

    const int bh = blockIdx.y;
    const int b  = bh / NH, h = bh % NH;
    const int q0 = blockIdx.x * 128;
    const long base = (long)b * SQ * DM + (long)h * DH;

    const int tid  = threadIdx.x;
    const int warp = tid >> 5, lane = tid & 31;

    // ---- Q tile f32 -> fp16 smem (128 rows x 64): 16 float4 per thread
    #pragma unroll
    for (int i = 0; i < 16; i++) {
        int linear = i * 128 + tid;
        int r = linear >> 4, dq = (linear & 15) * 4;
        float4 t = *(const float4*)&Q[base + (long)(q0 + r) * DM + dq];
        __half2* dst = (__half2*)&sm.q[r][dq];
        dst[0] = __floats2half2_rn(t.x, t.y);
        dst[1] = __floats2half2_rn(t.z, t.w);
    }
    __syncthreads();

    // ---- Q fragments: warp rows [32w, 32w+32) as two 16-row tiles
    uint32_t qf[2][4][4];
    #pragma unroll
    for (int rt = 0; rt < 2; rt++)
        #pragma unroll
        for (int kc = 0; kc < 4; kc++) {
            uint32_t addr = smem_u32(
                &sm.q[warp * 32 + rt * 16 + (lane & 15)][kc * 16 + (lane >> 4) * 8]);
            LDMX4(qf[rt][kc][0], qf[rt][kc][1], qf[rt][kc][2], qf[rt][kc][3], addr);
        }
    __syncthreads();   // Q smem consumed; safe to overwrite with K/V

    float o[2][8][4];
    #pragma unroll
    for (int rt = 0; rt < 2; rt++)
        #pragma unroll
        for (int nt = 0; nt < 8; nt++)
            #pragma unroll
            for (int r = 0; r < 4; r++) o[rt][nt][r] = 0.0f;
    float m_lo[2] = {-3.0e38f, -3.0e38f}, m_hi[2] = {-3.0e38f, -3.0e38f};
    float l_lo[2] = {0.0f, 0.0f},         l_hi[2] = {0.0f, 0.0f};

    for (int c0 = 0; c0 < SQ; c0 += 64) {
        // ---- K tile natural [key][dh]: 8 float4 per thread
        #pragma unroll
        for (int i = 0; i < 8; i++) {
            int linear = i * 128 + tid;
            int c = linear >> 4, dq = (linear & 15) * 4;
            float4 t = *(const float4*)&K[base + (long)(c0 + c) * DM + dq];
            __half2* dst = (__half2*)&sm.kv.k[c][dq];
            dst[0] = __floats2half2_rn(t.x, t.y);
            dst[1] = __floats2half2_rn(t.z, t.w);
        }
        // ---- V tile transposed + swizzled [dh][key^((dh&7)<<3)]
        #pragma unroll
        for (int i = 0; i < 8; i++) {
            int linear = i * 128 + tid;
            int c = linear >> 4, dq = (linear & 15) * 4;
            float4 t = *(const float4*)&V[base + (long)(c0 + c) * DM + dq];
            sm.kv.v[dq + 0][c ^ (((dq + 0) & 7) << 3)] = __float2half(t.x);
            sm.kv.v[dq + 1][c ^ (((dq + 1) & 7) << 3)] = __float2half(t.y);
            sm.kv.v[dq + 2][c ^ (((dq + 2) & 7) << 3)] = __float2half(t.z);
            sm.kv.v[dq + 3][c ^ (((dq + 3) & 7) << 3)] = __float2half(t.w);
        }
        __syncthreads();

        // ---- S = Q @ K^T, K-frags hoisted per kc and shared across rt
        float s[2][8][4];
        #pragma unroll
        for (int rt = 0; rt < 2; rt++)
            #pragma unroll
            for (int nt = 0; nt < 8; nt++)
                #pragma unroll
                for (int r = 0; r < 4; r++) s[rt][nt][r] = 0.0f;

        #pragma unroll
        for (int kc = 0; kc < 4; kc++) {
            uint32_t br[4][4];
            #pragma unroll
            for (int nt2 = 0; nt2 < 4; nt2++) {
                uint32_t addr = smem_u32(
                    &sm.kv.k[nt2 * 16 + (lane & 15)][kc * 16 + (lane >> 4) * 8]);
                LDMX4(br[nt2][0], br[nt2][1], br[nt2][2], br[nt2][3], addr);
            }
            #pragma unroll
            for (int rt = 0; rt < 2; rt++)
                #pragma unroll
                for (int nt = 0; nt < 8; nt++)
                    MMA16816(s[rt][nt], qf[rt][kc],
                             br[nt >> 1][nt & 1], br[nt >> 1][(nt & 1) + 2]);
        }

        // ---- online softmax per row-tile (logit = s * 0.125)
        uint32_t pp[2][8][2];
        #pragma unroll
        for (int rt = 0; rt < 2; rt++) {
            float mt_lo = -3.0e38f, mt_hi = -3.0e38f;
            #pragma unroll
            for (int nt = 0; nt < 8; nt++) {
                mt_lo = fmaxf(mt_lo, fmaxf(s[rt][nt][0], s[rt][nt][1]));
                mt_hi = fmaxf(mt_hi, fmaxf(s[rt][nt][2], s[rt][nt][3]));
            }
            mt_lo *= 0.125f; mt_hi *= 0.125f;
            mt_lo = fmaxf(mt_lo, __shfl_xor_sync(0xffffffffu, mt_lo, 1));
            mt_lo = fmaxf(mt_lo, __shfl_xor_sync(0xffffffffu, mt_lo, 2));
            mt_hi = fmaxf(mt_hi, __shfl_xor_sync(0xffffffffu, mt_hi, 1));
            mt_hi = fmaxf(mt_hi, __shfl_xor_sync(0xffffffffu, mt_hi, 2));

            const float mn_lo = fmaxf(m_lo[rt], mt_lo);
            const float mn_hi = fmaxf(m_hi[rt], mt_hi);
            const float corr_lo = __expf(m_lo[rt] - mn_lo);
            const float corr_hi = __expf(m_hi[rt] - mn_hi);
            m_lo[rt] = mn_lo; m_hi[rt] = mn_hi;

            float rs_lo = 0.0f, rs_hi = 0.0f;
            #pragma unroll
            for (int nt = 0; nt < 8; nt++) {
                float p0 = __expf(fmaf(s[rt][nt][0], 0.125f, -mn_lo));
                float p1 = __expf(fmaf(s[rt][nt][1], 0.125f, -mn_lo));
                float p2 = __expf(fmaf(s[rt][nt][2], 0.125f, -mn_hi));
                float p3 = __expf(fmaf(s[rt][nt][3], 0.125f, -mn_hi));
                rs_lo += p0 + p1; rs_hi += p2 + p3;
                __half2 h01 = __floats2half2_rn(p0, p1);
                __half2 h23 = __floats2half2_rn(p2, p3);
                pp[rt][nt][0] = *(uint32_t*)&h01;
                pp[rt][nt][1] = *(uint32_t*)&h23;
            }
            rs_lo += __shfl_xor_sync(0xffffffffu, rs_lo, 1);
            rs_lo += __shfl_xor_sync(0xffffffffu, rs_lo, 2);
            rs_hi += __shfl_xor_sync(0xffffffffu, rs_hi, 1);
            rs_hi += __shfl_xor_sync(0xffffffffu, rs_hi, 2);
            l_lo[rt] = l_lo[rt] * corr_lo + rs_lo;
            l_hi[rt] = l_hi[rt] * corr_hi + rs_hi;
            #pragma unroll
            for (int nt = 0; nt < 8; nt++) {
                o[rt][nt][0] *= corr_lo; o[rt][nt][1] *= corr_lo;
                o[rt][nt][2] *= corr_hi; o[rt][nt][3] *= corr_hi;
            }
        }

        // ---- O += P @ V, V-frags hoisted per kc and shared across rt
        #pragma unroll
        for (int kc = 0; kc < 4; kc++) {
            uint32_t br[4][4];
            #pragma unroll
            for (int nt2 = 0; nt2 < 4; nt2++) {
                int row = nt2 * 16 + (lane & 15);
                uint32_t addr = smem_u32(
                    &sm.kv.v[row][(kc * 16 + (lane >> 4) * 8) ^ ((row & 7) << 3)]);
                LDMX4(br[nt2][0], br[nt2][1], br[nt2][2], br[nt2][3], addr);
            }
            #pragma unroll
            for (int rt = 0; rt < 2; rt++) {
                uint32_t a[4] = { pp[rt][2 * kc][0], pp[rt][2 * kc][1],
                                  pp[rt][2 * kc + 1][0], pp[rt][2 * kc + 1][1] };
                #pragma unroll
                for (int nt = 0; nt < 8; nt++)
                    MMA16816(o[rt][nt], a,
                             br[nt >> 1][nt & 1], br[nt >> 1][(nt & 1) + 2]);
            }
        }
        __syncthreads();   // K/V consumed before next tile overwrites
    }

    // ---- epilogue
    #pragma unroll
    for (int rt = 0; rt < 2; rt++) {
        const float inv_lo = 1.0f / l_lo[rt], inv_hi = 1.0f / l_hi[rt];
        const long row_lo = q0 + warp * 32 + rt * 16 + (lane >> 2);
        #pragma unroll
        for (int nt = 0; nt < 8; nt++) {
            int col = nt * 8 + 2 * (lane & 3);
            *(float2*)&O[base + row_lo * DM + col] =
                make_float2(o[rt][nt][0] * inv_lo, o[rt][nt][1] * inv_lo);
            *(float2*)&O[base + (row_lo + 8) * DM + col] =
                make_float2(o[rt][nt][2] * inv_hi, o[rt][nt][3] * inv_hi);
        }
    }
}

// ---------------------------------------------------------------------------
// LayerNorm over rows of length 1024
// ---------------------------------------------------------------------------
__global__ void __launch_bounds__(256)
layernorm1024(const float* __restrict__ x, const float* __restrict__ g,
              const float* __restrict__ b, float* __restrict__ out)
{
    const long row = blockIdx.x;
    const float* p = x + row * (long)DM;
    float v[4];
    float s = 0.0f;
    #pragma unroll
    for (int i = 0; i < 4; i++) {
        v[i] = p[threadIdx.x + i * 256];
        s += v[i];
    }
    s = block_reduce_sum(s);
    const float mean = s * (1.0f / DM);
    float s2 = 0.0f;
    #pragma unroll
    for (int i = 0; i < 4; i++) {
        float d = v[i] - mean;
        s2 += d * d;
    }
    s2 = block_reduce_sum(s2);
    const float rstd = rsqrtf(s2 * (1.0f / DM) + 1e-5f);
    #pragma unroll
    for (int i = 0; i < 4; i++) {
        int c = threadIdx.x + i * 256;
        out[row * (long)DM + c] = (v[i] - mean) * rstd * g[c] + b[c];
    }
}

// ---------------------------------------------------------------------------
// Launch orchestration (graph-capturable: kernel launches only)
// ---------------------------------------------------------------------------
extern "C" void kernel_launch(void* const* d_in, const int* in_sizes, int n_in,
                              void* d_out, int out_size)
{
    const float* src   = (const float*)d_in[0];
    const float* qw    = (const float*)d_in[1];
    const float* qb    = (const float*)d_in[2];
    const float* kw    = (const float*)d_in[3];
    const float* kb    = (const float*)d_in[4];
    const float* vw    = (const float*)d_in[5];
    const float* vb    = (const float*)d_in[6];
    const float* ow    = (const float*)d_in[7];
    const float* ob    = (const float*)d_in[8];
    const float* w1    = (const float*)d_in[9];
    const float* b1    = (const float*)d_in[10];
    const float* w2    = (const float*)d_in[11];
    const float* b2    = (const float*)d_in[12];
    const float* g1    = (const float*)d_in[13];
    const float* beta1 = (const float*)d_in[14];
    const float* g2    = (const float*)d_in[15];
    const float* beta2 = (const float*)d_in[16];
    float* out = (float*)d_out;

    float *ga, *gb, *gc, *gf;
    cudaGetSymbolAddress((void**)&ga, g_a);
    cudaGetSymbolAddress((void**)&gb, g_b);
    cudaGetSymbolAddress((void**)&gc, g_c);
    cudaGetSymbolAddress((void**)&gf, g_f);

    const dim3 blk(256);

    // ---- QKV projections
    {
        dim3 g(DM / 128, MROWS / 128);
        gemm_hmma<false,false><<<g, blk>>>(
            src, DM, qw, DM, qb, nullptr, ga, DM, MROWS, DM, DM);
        gemm_hmma<false,false><<<g, blk>>>(
            src, DM, kw, DM, kb, nullptr, gb, DM, MROWS, DM, DM);
        gemm_hmma<false,false><<<g, blk>>>(
            src, DM, vw, DM, vb, nullptr, gc, DM, MROWS, DM, DM);
    }

    // ---- fused attention (tensor cores); ctx aliases q in ga
    {
        dim3 g(SQ / 128, BZ * NH);
        flash_hmma<<<g, dim3(128)>>>(ga, gb, gc, ga);
    }

    // ---- O projection + residual
    {
        dim3 g(DM / 128, MROWS / 128);
        gemm_hmma<false,true><<<g, blk>>>(
            ga, DM, ow, DM, ob, src, gb, DM, MROWS, DM, DM);
    }

    // ---- LN1
    layernorm1024<<<MROWS, blk>>>(gb, g1, beta1, gc);

    // ---- FF1
    {
        dim3 g(FFD / 128, MROWS / 128);
        gemm_hmma<true,false><<<g, blk>>>(
            gc, DM, w1, DM, b1, nullptr, gf, FFD, MROWS, FFD, DM);
    }

    // ---- FF2 + residual
    {
        dim3 g(DM / 128, MROWS / 128);
        gemm_hmma<false,true><<<g, blk>>>(
            gf, FFD, w2, FFD, b2, gc, ga, DM, MROWS, DM, FFD);
    }

    // ---- LN2 -> output
    layernorm1024<<<MROWS, blk>>>(ga, g2, beta2, out);
}

// round 11
// speedup vs baseline: 7.0068x; 1.3011x over previous
#include <cuda_runtime.h>
#include <cuda_fp16.h>
#include <cstdint>

// ---------------------------------------------------------------------------
// Problem constants
// ---------------------------------------------------------------------------
#define BZ   2
#define SQ   2048
#define DM   1024
#define NH   16
#define DH   64
#define FFD  4096
#define MROWS (BZ * SQ)            // 4096

// ---------------------------------------------------------------------------
// Scratch (device globals). 136 MB total.
//   qh/kh/vh: fp16 QKV (written by projection GEMMs, read by flash)
//   g_t0: ctx (flash out) -> y2 (FF2 out);  g_t1: y;  g_t2: x1;  g_tf: ffh
// ---------------------------------------------------------------------------
__device__ __half g_qh[(size_t)MROWS * DM];
__device__ __half g_kh[(size_t)MROWS * DM];
__device__ __half g_vh[(size_t)MROWS * DM];
__device__ float  g_t0[(size_t)MROWS * DM];
__device__ float  g_t1[(size_t)MROWS * DM];
__device__ float  g_t2[(size_t)MROWS * DM];
__device__ float  g_tf[(size_t)MROWS * FFD];

// ---------------------------------------------------------------------------
// Helpers
// ---------------------------------------------------------------------------
__device__ __forceinline__ uint32_t smem_u32(const void* p) {
    return (uint32_t)__cvta_generic_to_shared(p);
}

#define LDMX4(r0, r1, r2, r3, addr)                                         \
    asm volatile("ldmatrix.sync.aligned.m8n8.x4.shared.b16 {%0,%1,%2,%3}, [%4];" \
                 : "=r"(r0), "=r"(r1), "=r"(r2), "=r"(r3) : "r"(addr))

#define LDMX4T(r0, r1, r2, r3, addr)                                        \
    asm volatile("ldmatrix.sync.aligned.m8n8.x4.trans.shared.b16 {%0,%1,%2,%3}, [%4];" \
                 : "=r"(r0), "=r"(r1), "=r"(r2), "=r"(r3) : "r"(addr))

#define MMA16816(d, a, b0, b1)                                              \
    asm volatile("mma.sync.aligned.m16n8k16.row.col.f32.f16.f16.f32 "        \
                 "{%0,%1,%2,%3}, {%4,%5,%6,%7}, {%8,%9}, {%0,%1,%2,%3};"     \
                 : "+f"(d[0]), "+f"(d[1]), "+f"(d[2]), "+f"(d[3])            \
                 : "r"(a[0]), "r"(a[1]), "r"(a[2]), "r"(a[3]),               \
                   "r"(b0), "r"(b1))

#define CP_ASYNC16(dst, src)                                                \
    asm volatile("cp.async.cg.shared.global [%0], [%1], 16;"                 \
                 :: "r"(dst), "l"(src))
#define CP_COMMIT  asm volatile("cp.async.commit_group;")
#define CP_WAIT0   asm volatile("cp.async.wait_group 0;")
#define CP_WAIT1   asm volatile("cp.async.wait_group 1;")

// swizzled byte offset within a 64-half-wide (128B) row tile
__device__ __forceinline__ uint32_t swz(int r, int c16) {
    return (uint32_t)(r * 128 + ((c16 ^ (r & 7)) * 16));
}

__device__ __forceinline__ void store2(float* C, long idx, float v0, float v1) {
    *(float2*)&C[idx] = make_float2(v0, v1);
}
__device__ __forceinline__ void store2(__half* C, long idx, float v0, float v1) {
    *(__half2*)&C[idx] = __floats2half2_rn(v0, v1);
}

__device__ __forceinline__ float block_reduce_sum(float v) {
    __shared__ float sh[32];
    const unsigned mask = 0xffffffffu;
    #pragma unroll
    for (int o = 16; o > 0; o >>= 1) v += __shfl_xor_sync(mask, v, o);
    int lane = threadIdx.x & 31, w = threadIdx.x >> 5;
    __syncthreads();
    if (lane == 0) sh[w] = v;
    __syncthreads();
    int nw = (blockDim.x + 31) >> 5;
    if (w == 0) {
        v = (lane < nw) ? sh[lane] : 0.0f;
        #pragma unroll
        for (int o = 16; o > 0; o >>= 1) v += __shfl_xor_sync(mask, v, o);
        if (lane == 0) sh[0] = v;
    }
    __syncthreads();
    return sh[0];
}

// ---------------------------------------------------------------------------
// HMMA GEMM (TN): C(OutT) = A @ B^T [+ bias] [+ resid], optional ReLU.
// A,B f32; accumulate f32; OutT = float or __half.
// ---------------------------------------------------------------------------
template<bool RELU, bool RESID, typename OutT>
__global__ void __launch_bounds__(256, 2)
gemm_hmma(const float* __restrict__ A, int lda,
          const float* __restrict__ B, int ldb,
          const float* __restrict__ bias,
          const float* __restrict__ resid,
          OutT* __restrict__ C, int ldc,
          int M, int N, int K)
{
    constexpr int BK = 64;
    constexpr int LDS = BK + 8;
    __shared__ __align__(16) __half As[128][LDS];
    __shared__ __align__(16) __half Bs[128][LDS];

    const int tid  = threadIdx.x;
    const int warp = tid >> 5, lane = tid & 31;
    const int wm = warp >> 2;
    const int wn = warp & 3;
    const int row0 = blockIdx.y * 128;
    const int col0 = blockIdx.x * 128;

    float acc[4][4][4];
    #pragma unroll
    for (int mt = 0; mt < 4; mt++)
        #pragma unroll
        for (int nt = 0; nt < 4; nt++)
            #pragma unroll
            for (int r = 0; r < 4; r++) acc[mt][nt][r] = 0.0f;

    for (int k0 = 0; k0 < K; k0 += BK) {
        #pragma unroll
        for (int i = 0; i < 8; i++) {
            int linear = (i * 256 + tid) * 4;
            int r = linear >> 6, c = linear & 63;
            float4 t = *(const float4*)&A[(long)(row0 + r) * lda + k0 + c];
            __half2* dst = (__half2*)&As[r][c];
            dst[0] = __floats2half2_rn(t.x, t.y);
            dst[1] = __floats2half2_rn(t.z, t.w);
        }
        #pragma unroll
        for (int i = 0; i < 8; i++) {
            int linear = (i * 256 + tid) * 4;
            int r = linear >> 6, c = linear & 63;
            float4 t = *(const float4*)&B[(long)(col0 + r) * ldb + k0 + c];
            __half2* dst = (__half2*)&Bs[r][c];
            dst[0] = __floats2half2_rn(t.x, t.y);
            dst[1] = __floats2half2_rn(t.z, t.w);
        }
        __syncthreads();

        #pragma unroll
        for (int ks = 0; ks < 4; ks++) {
            const int kk = ks * 16;
            uint32_t a[4][4], br[2][4];
            #pragma unroll
            for (int mt = 0; mt < 4; mt++) {
                uint32_t addr = smem_u32(
                    &As[wm * 64 + mt * 16 + (lane & 15)][kk + (lane >> 4) * 8]);
                LDMX4(a[mt][0], a[mt][1], a[mt][2], a[mt][3], addr);
            }
            #pragma unroll
            for (int nt2 = 0; nt2 < 2; nt2++) {
                uint32_t addr = smem_u32(
                    &Bs[wn * 32 + nt2 * 16 + (lane & 15)][kk + (lane >> 4) * 8]);
                LDMX4(br[nt2][0], br[nt2][1], br[nt2][2], br[nt2][3], addr);
            }
            #pragma unroll
            for (int mt = 0; mt < 4; mt++)
                #pragma unroll
                for (int nt = 0; nt < 4; nt++) {
                    uint32_t b0 = br[nt >> 1][(nt & 1)];
                    uint32_t b1 = br[nt >> 1][(nt & 1) + 2];
                    MMA16816(acc[mt][nt], a[mt], b0, b1);
                }
        }
        __syncthreads();
    }

    #pragma unroll
    for (int mt = 0; mt < 4; mt++) {
        int r0w = row0 + wm * 64 + mt * 16 + (lane >> 2);
        #pragma unroll
        for (int nt = 0; nt < 4; nt++) {
            int cn = col0 + wn * 32 + nt * 8 + 2 * (lane & 3);
            float v0 = acc[mt][nt][0], v1 = acc[mt][nt][1];
            float v2 = acc[mt][nt][2], v3 = acc[mt][nt][3];
            if (bias) {
                float b0v = bias[cn], b1v = bias[cn + 1];
                v0 += b0v; v1 += b1v; v2 += b0v; v3 += b1v;
            }
            if (RESID) {
                v0 += resid[(long)r0w * ldc + cn];
                v1 += resid[(long)r0w * ldc + cn + 1];
                v2 += resid[(long)(r0w + 8) * ldc + cn];
                v3 += resid[(long)(r0w + 8) * ldc + cn + 1];
            }
            if (RELU) {
                v0 = fmaxf(v0, 0.0f); v1 = fmaxf(v1, 0.0f);
                v2 = fmaxf(v2, 0.0f); v3 = fmaxf(v3, 0.0f);
            }
            store2(C, (long)r0w * ldc + cn, v0, v1);
            store2(C, (long)(r0w + 8) * ldc + cn, v2, v3);
        }
    }
}

// ---------------------------------------------------------------------------
// Flash attention v3: fp16 Q/K/V in gmem, cp.async + XOR-swizzled smem,
// ldmatrix.trans for V (no smem transpose), double-buffered K/V stages.
// 128 threads (4 warps x 32 query rows), BR=128, BC=64. Output ctx f32.
// ---------------------------------------------------------------------------
__global__ void __launch_bounds__(128)
flash_hmma(const __half* __restrict__ Q, const __half* __restrict__ K,
           const __half* __restrict__ V, float* __restrict__ O)
{
    __shared__ __align__(16) union SmemU {
        __half q[128 * 64];                              // 16 KB (Q phase)
        struct { __half k[2][64 * 64]; __half v[2][64 * 64]; } s;  // 32 KB
    } sm;

    const int bh = blockIdx.y;
    const int b  = bh / NH, h = bh % NH;
    const int q0 = blockIdx.x * 128;
    const long base = (long)b * SQ * DM + (long)h * DH;

    const int tid  = threadIdx.x;
    const int warp = tid >> 5, lane = tid & 31;

    // ---- Q tile via cp.async (128 rows x 8 chunks of 16B)
    {
        uint32_t qs = smem_u32(sm.q);
        #pragma unroll
        for (int i = 0; i < 8; i++) {
            int linear = i * 128 + tid;
            int r = linear >> 3, c16 = linear & 7;
            CP_ASYNC16(qs + swz(r, c16),
                       Q + base + (long)(q0 + r) * DM + c16 * 8);
        }
        CP_COMMIT; CP_WAIT0;
        __syncthreads();
    }

    // ---- Q fragments: warp rows [32w, 32w+32) as two 16-row tiles
    uint32_t qf[2][4][4];
    {
        uint32_t qs = smem_u32(sm.q);
        #pragma unroll
        for (int rt = 0; rt < 2; rt++)
            #pragma unroll
            for (int kc = 0; kc < 4; kc++) {
                int row = warp * 32 + rt * 16 + (lane & 15);
                uint32_t addr = qs + swz(row, kc * 2 + (lane >> 4));
                LDMX4(qf[rt][kc][0], qf[rt][kc][1], qf[rt][kc][2], qf[rt][kc][3], addr);
            }
    }
    __syncthreads();   // Q smem consumed; stages may overwrite

    float o[2][8][4];
    #pragma unroll
    for (int rt = 0; rt < 2; rt++)
        #pragma unroll
        for (int nt = 0; nt < 8; nt++)
            #pragma unroll
            for (int r = 0; r < 4; r++) o[rt][nt][r] = 0.0f;
    float m_lo[2] = {-3.0e38f, -3.0e38f}, m_hi[2] = {-3.0e38f, -3.0e38f};
    float l_lo[2] = {0.0f, 0.0f},         l_hi[2] = {0.0f, 0.0f};

    // K/V stage loader: 64 rows x 8 chunks each => 4 chunks/thread/tensor
    auto kvload = [&](int stg, int c0) {
        uint32_t ks = smem_u32(sm.s.k[stg]);
        uint32_t vs = smem_u32(sm.s.v[stg]);
        #pragma unroll
        for (int i = 0; i < 4; i++) {
            int linear = i * 128 + tid;
            int r = linear >> 3, c16 = linear & 7;
            CP_ASYNC16(ks + swz(r, c16), K + base + (long)(c0 + r) * DM + c16 * 8);
        }
        #pragma unroll
        for (int i = 0; i < 4; i++) {
            int linear = i * 128 + tid;
            int r = linear >> 3, c16 = linear & 7;
            CP_ASYNC16(vs + swz(r, c16), V + base + (long)(c0 + r) * DM + c16 * 8);
        }
    };

    kvload(0, 0);
    CP_COMMIT;

    const int NT = SQ / 64;            // 32 tiles
    for (int t = 0; t < NT; t++) {
        if (t + 1 < NT) { kvload((t + 1) & 1, (t + 1) * 64); CP_COMMIT; CP_WAIT1; }
        else            { CP_WAIT0; }
        __syncthreads();

        const uint32_t ks = smem_u32(sm.s.k[t & 1]);
        const uint32_t vs = smem_u32(sm.s.v[t & 1]);

        // ---- S = Q @ K^T
        float s[2][8][4];
        #pragma unroll
        for (int rt = 0; rt < 2; rt++)
            #pragma unroll
            for (int nt = 0; nt < 8; nt++)
                #pragma unroll
                for (int r = 0; r < 4; r++) s[rt][nt][r] = 0.0f;

        #pragma unroll
        for (int kc = 0; kc < 4; kc++) {
            uint32_t br[4][4];
            #pragma unroll
            for (int nt2 = 0; nt2 < 4; nt2++) {
                int row = nt2 * 16 + (lane & 15);
                uint32_t addr = ks + swz(row, kc * 2 + (lane >> 4));
                LDMX4(br[nt2][0], br[nt2][1], br[nt2][2], br[nt2][3], addr);
            }
            #pragma unroll
            for (int rt = 0; rt < 2; rt++)
                #pragma unroll
                for (int nt = 0; nt < 8; nt++)
                    MMA16816(s[rt][nt], qf[rt][kc],
                             br[nt >> 1][nt & 1], br[nt >> 1][(nt & 1) + 2]);
        }

        // ---- online softmax (logit = s * 0.125)
        uint32_t pp[2][8][2];
        #pragma unroll
        for (int rt = 0; rt < 2; rt++) {
            float mt_lo = -3.0e38f, mt_hi = -3.0e38f;
            #pragma unroll
            for (int nt = 0; nt < 8; nt++) {
                mt_lo = fmaxf(mt_lo, fmaxf(s[rt][nt][0], s[rt][nt][1]));
                mt_hi = fmaxf(mt_hi, fmaxf(s[rt][nt][2], s[rt][nt][3]));
            }
            mt_lo *= 0.125f; mt_hi *= 0.125f;
            mt_lo = fmaxf(mt_lo, __shfl_xor_sync(0xffffffffu, mt_lo, 1));
            mt_lo = fmaxf(mt_lo, __shfl_xor_sync(0xffffffffu, mt_lo, 2));
            mt_hi = fmaxf(mt_hi, __shfl_xor_sync(0xffffffffu, mt_hi, 1));
            mt_hi = fmaxf(mt_hi, __shfl_xor_sync(0xffffffffu, mt_hi, 2));

            const float mn_lo = fmaxf(m_lo[rt], mt_lo);
            const float mn_hi = fmaxf(m_hi[rt], mt_hi);
            const float corr_lo = __expf(m_lo[rt] - mn_lo);
            const float corr_hi = __expf(m_hi[rt] - mn_hi);
            m_lo[rt] = mn_lo; m_hi[rt] = mn_hi;

            float rs_lo = 0.0f, rs_hi = 0.0f;
            #pragma unroll
            for (int nt = 0; nt < 8; nt++) {
                float p0 = __expf(fmaf(s[rt][nt][0], 0.125f, -mn_lo));
                float p1 = __expf(fmaf(s[rt][nt][1], 0.125f, -mn_lo));
                float p2 = __expf(fmaf(s[rt][nt][2], 0.125f, -mn_hi));
                float p3 = __expf(fmaf(s[rt][nt][3], 0.125f, -mn_hi));
                rs_lo += p0 + p1; rs_hi += p2 + p3;
                __half2 h01 = __floats2half2_rn(p0, p1);
                __half2 h23 = __floats2half2_rn(p2, p3);
                pp[rt][nt][0] = *(uint32_t*)&h01;
                pp[rt][nt][1] = *(uint32_t*)&h23;
            }
            rs_lo += __shfl_xor_sync(0xffffffffu, rs_lo, 1);
            rs_lo += __shfl_xor_sync(0xffffffffu, rs_lo, 2);
            rs_hi += __shfl_xor_sync(0xffffffffu, rs_hi, 1);
            rs_hi += __shfl_xor_sync(0xffffffffu, rs_hi, 2);
            l_lo[rt] = l_lo[rt] * corr_lo + rs_lo;
            l_hi[rt] = l_hi[rt] * corr_hi + rs_hi;
            #pragma unroll
            for (int nt = 0; nt < 8; nt++) {
                o[rt][nt][0] *= corr_lo; o[rt][nt][1] *= corr_lo;
                o[rt][nt][2] *= corr_hi; o[rt][nt][3] *= corr_hi;
            }
        }

        // ---- O += P @ V via ldmatrix.trans on natural [key][dh] tiles
        #pragma unroll
        for (int kc = 0; kc < 4; kc++) {
            uint32_t vr[4][4];
            #pragma unroll
            for (int g2 = 0; g2 < 4; g2++) {
                int row = kc * 16 + (lane & 15);
                uint32_t addr = vs + swz(row, g2 * 2 + (lane >> 4));
                LDMX4T(vr[g2][0], vr[g2][1], vr[g2][2], vr[g2][3], addr);
            }
            #pragma unroll
            for (int rt = 0; rt < 2; rt++) {
                uint32_t a[4] = { pp[rt][2 * kc][0], pp[rt][2 * kc][1],
                                  pp[rt][2 * kc + 1][0], pp[rt][2 * kc + 1][1] };
                #pragma unroll
                for (int nt = 0; nt < 8; nt++)
                    MMA16816(o[rt][nt], a,
                             vr[nt >> 1][(nt & 1) * 2], vr[nt >> 1][(nt & 1) * 2 + 1]);
            }
        }
        __syncthreads();   // stage consumed before overwrite at t+2
    }

    // ---- epilogue (f32 ctx out)
    #pragma unroll
    for (int rt = 0; rt < 2; rt++) {
        const float inv_lo = 1.0f / l_lo[rt], inv_hi = 1.0f / l_hi[rt];
        const long row_lo = q0 + warp * 32 + rt * 16 + (lane >> 2);
        #pragma unroll
        for (int nt = 0; nt < 8; nt++) {
            int col = nt * 8 + 2 * (lane & 3);
            *(float2*)&O[base + row_lo * DM + col] =
                make_float2(o[rt][nt][0] * inv_lo, o[rt][nt][1] * inv_lo);
            *(float2*)&O[base + (row_lo + 8) * DM + col] =
                make_float2(o[rt][nt][2] * inv_hi, o[rt][nt][3] * inv_hi);
        }
    }
}

// ---------------------------------------------------------------------------
// LayerNorm over rows of length 1024
// ---------------------------------------------------------------------------
__global__ void __launch_bounds__(256)
layernorm1024(const float* __restrict__ x, const float* __restrict__ g,
              const float* __restrict__ b, float* __restrict__ out)
{
    const long row = blockIdx.x;
    const float* p = x + row * (long)DM;
    float v[4];
    float s = 0.0f;
    #pragma unroll
    for (int i = 0; i < 4; i++) {
        v[i] = p[threadIdx.x + i * 256];
        s += v[i];
    }
    s = block_reduce_sum(s);
    const float mean = s * (1.0f / DM);
    float s2 = 0.0f;
    #pragma unroll
    for (int i = 0; i < 4; i++) {
        float d = v[i] - mean;
        s2 += d * d;
    }
    s2 = block_reduce_sum(s2);
    const float rstd = rsqrtf(s2 * (1.0f / DM) + 1e-5f);
    #pragma unroll
    for (int i = 0; i < 4; i++) {
        int c = threadIdx.x + i * 256;
        out[row * (long)DM + c] = (v[i] - mean) * rstd * g[c] + b[c];
    }
}

// ---------------------------------------------------------------------------
// Launch orchestration (graph-capturable: kernel launches only)
// ---------------------------------------------------------------------------
extern "C" void kernel_launch(void* const* d_in, const int* in_sizes, int n_in,
                              void* d_out, int out_size)
{
    const float* src   = (const float*)d_in[0];
    const float* qw    = (const float*)d_in[1];
    const float* qb    = (const float*)d_in[2];
    const float* kw    = (const float*)d_in[3];
    const float* kb    = (const float*)d_in[4];
    const float* vw    = (const float*)d_in[5];
    const float* vb    = (const float*)d_in[6];
    const float* ow    = (const float*)d_in[7];
    const float* ob    = (const float*)d_in[8];
    const float* w1    = (const float*)d_in[9];
    const float* b1    = (const float*)d_in[10];
    const float* w2    = (const float*)d_in[11];
    const float* b2    = (const float*)d_in[12];
    const float* g1    = (const float*)d_in[13];
    const float* beta1 = (const float*)d_in[14];
    const float* g2    = (const float*)d_in[15];
    const float* beta2 = (const float*)d_in[16];
    float* out = (float*)d_out;

    __half *qh, *kh, *vh;
    float *t0, *t1, *t2, *tf;
    cudaGetSymbolAddress((void**)&qh, g_qh);
    cudaGetSymbolAddress((void**)&kh, g_kh);
    cudaGetSymbolAddress((void**)&vh, g_vh);
    cudaGetSymbolAddress((void**)&t0, g_t0);
    cudaGetSymbolAddress((void**)&t1, g_t1);
    cudaGetSymbolAddress((void**)&t2, g_t2);
    cudaGetSymbolAddress((void**)&tf, g_tf);

    const dim3 blk(256);

    // ---- QKV projections -> fp16
    {
        dim3 g(DM / 128, MROWS / 128);
        gemm_hmma<false,false,__half><<<g, blk>>>(
            src, DM, qw, DM, qb, nullptr, qh, DM, MROWS, DM, DM);
        gemm_hmma<false,false,__half><<<g, blk>>>(
            src, DM, kw, DM, kb, nullptr, kh, DM, MROWS, DM, DM);
        gemm_hmma<false,false,__half><<<g, blk>>>(
            src, DM, vw, DM, vb, nullptr, vh, DM, MROWS, DM, DM);
    }

    // ---- fused attention: ctx(t0) = softmax(QK^T/8) V
    {
        dim3 g(SQ / 128, BZ * NH);
        flash_hmma<<<g, dim3(128)>>>(qh, kh, vh, t0);
    }

    // ---- O projection + residual: y(t1) = ctx @ ow^T + ob + src
    {
        dim3 g(DM / 128, MROWS / 128);
        gemm_hmma<false,true,float><<<g, blk>>>(
            t0, DM, ow, DM, ob, src, t1, DM, MROWS, DM, DM);
    }

    // ---- LN1: x1(t2) = LN(y)
    layernorm1024<<<MROWS, blk>>>(t1, g1, beta1, t2);

    // ---- FF1: ffh(tf) = relu(x1 @ w1^T + b1)
    {
        dim3 g(FFD / 128, MROWS / 128);
        gemm_hmma<true,false,float><<<g, blk>>>(
            t2, DM, w1, DM, b1, nullptr, tf, FFD, MROWS, FFD, DM);
    }

    // ---- FF2 + residual: y2(t0) = ffh @ w2^T + b2 + x1(t2)
    {
        dim3 g(DM / 128, MROWS / 128);
        gemm_hmma<false,true,float><<<g, blk>>>(
            tf, FFD, w2, FFD, b2, t2, t0, DM, MROWS, DM, FFD);
    }

    // ---- LN2 -> output
    layernorm1024<<<MROWS, blk>>>(t0, g2, beta2, out);
}

// round 12
// speedup vs baseline: 8.3496x; 1.1916x over previous
#include <cuda_runtime.h>
#include <cuda_fp16.h>
#include <cstdint>

// ---------------------------------------------------------------------------
// Problem constants
// ---------------------------------------------------------------------------
#define BZ   2
#define SQ   2048
#define DM   1024
#define NH   16
#define DH   64
#define FFD  4096
#define MROWS (BZ * SQ)            // 4096

// ---------------------------------------------------------------------------
// Scratch (device globals).
// ---------------------------------------------------------------------------
__device__ __half g_srch[(size_t)MROWS * DM];       // src fp16
__device__ __half g_qwh [(size_t)DM * DM];
__device__ __half g_kwh [(size_t)DM * DM];
__device__ __half g_vwh [(size_t)DM * DM];
__device__ __half g_owh [(size_t)DM * DM];
__device__ __half g_w1h [(size_t)FFD * DM];
__device__ __half g_w2h [(size_t)DM * FFD];
__device__ __half g_qh  [(size_t)MROWS * DM];
__device__ __half g_kh  [(size_t)MROWS * DM];
__device__ __half g_vh  [(size_t)MROWS * DM];
__device__ __half g_ctxh[(size_t)MROWS * DM];
__device__ __half g_x1h [(size_t)MROWS * DM];
__device__ __half g_ffh [(size_t)MROWS * FFD];      // fp16 hidden (32 MB)
__device__ float  g_t1  [(size_t)MROWS * DM];       // y
__device__ float  g_t2  [(size_t)MROWS * DM];       // x1 f32 (FF2 resid)
__device__ float  g_t0  [(size_t)MROWS * DM];       // y2

// ---------------------------------------------------------------------------
// Helpers
// ---------------------------------------------------------------------------
__device__ __forceinline__ uint32_t smem_u32(const void* p) {
    return (uint32_t)__cvta_generic_to_shared(p);
}

#define LDMX4(r0, r1, r2, r3, addr)                                         \
    asm volatile("ldmatrix.sync.aligned.m8n8.x4.shared.b16 {%0,%1,%2,%3}, [%4];" \
                 : "=r"(r0), "=r"(r1), "=r"(r2), "=r"(r3) : "r"(addr))

#define LDMX4T(r0, r1, r2, r3, addr)                                        \
    asm volatile("ldmatrix.sync.aligned.m8n8.x4.trans.shared.b16 {%0,%1,%2,%3}, [%4];" \
                 : "=r"(r0), "=r"(r1), "=r"(r2), "=r"(r3) : "r"(addr))

#define MMA16816(d, a, b0, b1)                                              \
    asm volatile("mma.sync.aligned.m16n8k16.row.col.f32.f16.f16.f32 "        \
                 "{%0,%1,%2,%3}, {%4,%5,%6,%7}, {%8,%9}, {%0,%1,%2,%3};"     \
                 : "+f"(d[0]), "+f"(d[1]), "+f"(d[2]), "+f"(d[3])            \
                 : "r"(a[0]), "r"(a[1]), "r"(a[2]), "r"(a[3]),               \
                   "r"(b0), "r"(b1))

#define CP_ASYNC16(dst, src)                                                \
    asm volatile("cp.async.cg.shared.global [%0], [%1], 16;"                 \
                 :: "r"(dst), "l"(src))
#define CP_COMMIT  asm volatile("cp.async.commit_group;")
#define CP_WAIT0   asm volatile("cp.async.wait_group 0;")
#define CP_WAIT1   asm volatile("cp.async.wait_group 1;")

// swizzled byte offset within a 64-half-wide (128B) row tile
__device__ __forceinline__ uint32_t swz(int r, int c16) {
    return (uint32_t)(r * 128 + ((c16 ^ (r & 7)) * 16));
}

__device__ __forceinline__ void store2(float* C, long idx, float v0, float v1) {
    *(float2*)&C[idx] = make_float2(v0, v1);
}
__device__ __forceinline__ void store2(__half* C, long idx, float v0, float v1) {
    *(__half2*)&C[idx] = __floats2half2_rn(v0, v1);
}

__device__ __forceinline__ float block_reduce_sum(float v) {
    __shared__ float sh[32];
    const unsigned mask = 0xffffffffu;
    #pragma unroll
    for (int o = 16; o > 0; o >>= 1) v += __shfl_xor_sync(mask, v, o);
    int lane = threadIdx.x & 31, w = threadIdx.x >> 5;
    __syncthreads();
    if (lane == 0) sh[w] = v;
    __syncthreads();
    int nw = (blockDim.x + 31) >> 5;
    if (w == 0) {
        v = (lane < nw) ? sh[lane] : 0.0f;
        #pragma unroll
        for (int o = 16; o > 0; o >>= 1) v += __shfl_xor_sync(mask, v, o);
        if (lane == 0) sh[0] = v;
    }
    __syncthreads();
    return sh[0];
}

// ---------------------------------------------------------------------------
// f32 -> f16 convert (n multiple of 1024)
// ---------------------------------------------------------------------------
__global__ void __launch_bounds__(256)
f32tof16(const float* __restrict__ in, __half* __restrict__ out)
{
    long i = ((long)blockIdx.x * 256 + threadIdx.x) * 4;
    float4 t = *(const float4*)&in[i];
    __half2* d = (__half2*)&out[i];
    d[0] = __floats2half2_rn(t.x, t.y);
    d[1] = __floats2half2_rn(t.z, t.w);
}

// ---------------------------------------------------------------------------
// Pipelined fp16 GEMM (TN): C(OutT) = A @ B^T [+ bias(f32)] [+ resid(f32)].
// A [M,K] fp16, B [N,K] fp16, both K-major. cp.async double-buffered stages,
// XOR-swizzled smem, fp32 accumulate. 256 thr, tile 128x128x64.
// Dynamic smem: 64 KB (2 stages x (A 16KB + B 16KB)).
// ---------------------------------------------------------------------------
template<bool RELU, bool RESID, typename OutT>
__global__ void __launch_bounds__(256, 2)
gemm16(const __half* __restrict__ A, int lda,
       const __half* __restrict__ B, int ldb,
       const float* __restrict__ bias,
       const float* __restrict__ resid,
       OutT* __restrict__ C, int ldc,
       int M, int N, int K)
{
    extern __shared__ __half smem[];
    __half* Asm = smem;                 // [2][128*64]
    __half* Bsm = smem + 2 * 128 * 64;  // [2][128*64]

    const int tid  = threadIdx.x;
    const int warp = tid >> 5, lane = tid & 31;
    const int wm = warp >> 2;           // 0..1
    const int wn = warp & 3;            // 0..3
    const int row0 = blockIdx.y * 128;
    const int col0 = blockIdx.x * 128;

    auto load = [&](int stg, int k0) {
        uint32_t as = smem_u32(Asm + stg * 128 * 64);
        uint32_t bs = smem_u32(Bsm + stg * 128 * 64);
        #pragma unroll
        for (int i = 0; i < 4; i++) {
            int linear = i * 256 + tid;
            int r = linear >> 3, c16 = linear & 7;
            CP_ASYNC16(as + swz(r, c16), A + (long)(row0 + r) * lda + k0 + c16 * 8);
        }
        #pragma unroll
        for (int i = 0; i < 4; i++) {
            int linear = i * 256 + tid;
            int r = linear >> 3, c16 = linear & 7;
            CP_ASYNC16(bs + swz(r, c16), B + (long)(col0 + r) * ldb + k0 + c16 * 8);
        }
    };

    float acc[4][4][4];
    #pragma unroll
    for (int mt = 0; mt < 4; mt++)
        #pragma unroll
        for (int nt = 0; nt < 4; nt++)
            #pragma unroll
            for (int r = 0; r < 4; r++) acc[mt][nt][r] = 0.0f;

    load(0, 0);
    CP_COMMIT;

    const int NSTEP = K / 64;
    for (int t = 0; t < NSTEP; t++) {
        if (t + 1 < NSTEP) { load((t + 1) & 1, (t + 1) * 64); CP_COMMIT; CP_WAIT1; }
        else               { CP_WAIT0; }
        __syncthreads();

        const uint32_t as = smem_u32(Asm + (t & 1) * 128 * 64);
        const uint32_t bs = smem_u32(Bsm + (t & 1) * 128 * 64);

        #pragma unroll
        for (int ks = 0; ks < 4; ks++) {
            uint32_t a[4][4], br[2][4];
            #pragma unroll
            for (int mt = 0; mt < 4; mt++) {
                int row = wm * 64 + mt * 16 + (lane & 15);
                uint32_t addr = as + swz(row, ks * 2 + (lane >> 4));
                LDMX4(a[mt][0], a[mt][1], a[mt][2], a[mt][3], addr);
            }
            #pragma unroll
            for (int nt2 = 0; nt2 < 2; nt2++) {
                int row = wn * 32 + nt2 * 16 + (lane & 15);
                uint32_t addr = bs + swz(row, ks * 2 + (lane >> 4));
                LDMX4(br[nt2][0], br[nt2][1], br[nt2][2], br[nt2][3], addr);
            }
            #pragma unroll
            for (int mt = 0; mt < 4; mt++)
                #pragma unroll
                for (int nt = 0; nt < 4; nt++) {
                    uint32_t b0 = br[nt >> 1][(nt & 1)];
                    uint32_t b1 = br[nt >> 1][(nt & 1) + 2];
                    MMA16816(acc[mt][nt], a[mt], b0, b1);
                }
        }
        __syncthreads();
    }

    #pragma unroll
    for (int mt = 0; mt < 4; mt++) {
        int r0w = row0 + wm * 64 + mt * 16 + (lane >> 2);
        #pragma unroll
        for (int nt = 0; nt < 4; nt++) {
            int cn = col0 + wn * 32 + nt * 8 + 2 * (lane & 3);
            float v0 = acc[mt][nt][0], v1 = acc[mt][nt][1];
            float v2 = acc[mt][nt][2], v3 = acc[mt][nt][3];
            if (bias) {
                float b0v = bias[cn], b1v = bias[cn + 1];
                v0 += b0v; v1 += b1v; v2 += b0v; v3 += b1v;
            }
            if (RESID) {
                v0 += resid[(long)r0w * ldc + cn];
                v1 += resid[(long)r0w * ldc + cn + 1];
                v2 += resid[(long)(r0w + 8) * ldc + cn];
                v3 += resid[(long)(r0w + 8) * ldc + cn + 1];
            }
            if (RELU) {
                v0 = fmaxf(v0, 0.0f); v1 = fmaxf(v1, 0.0f);
                v2 = fmaxf(v2, 0.0f); v3 = fmaxf(v3, 0.0f);
            }
            store2(C, (long)r0w * ldc + cn, v0, v1);
            store2(C, (long)(r0w + 8) * ldc + cn, v2, v3);
        }
    }
}

// ---------------------------------------------------------------------------
// Flash attention v3 (unchanged except fp16 ctx output).
// 128 threads (4 warps x 32 query rows), BR=128, BC=64, cp.async + swizzle,
// ldmatrix.trans for V, double-buffered K/V stages.
// ---------------------------------------------------------------------------
__global__ void __launch_bounds__(128)
flash_hmma(const __half* __restrict__ Q, const __half* __restrict__ K,
           const __half* __restrict__ V, __half* __restrict__ O)
{
    __shared__ __align__(16) union SmemU {
        __half q[128 * 64];
        struct { __half k[2][64 * 64]; __half v[2][64 * 64]; } s;
    } sm;

    const int bh = blockIdx.y;
    const int b  = bh / NH, h = bh % NH;
    const int q0 = blockIdx.x * 128;
    const long base = (long)b * SQ * DM + (long)h * DH;

    const int tid  = threadIdx.x;
    const int warp = tid >> 5, lane = tid & 31;

    {
        uint32_t qs = smem_u32(sm.q);
        #pragma unroll
        for (int i = 0; i < 8; i++) {
            int linear = i * 128 + tid;
            int r = linear >> 3, c16 = linear & 7;
            CP_ASYNC16(qs + swz(r, c16),
                       Q + base + (long)(q0 + r) * DM + c16 * 8);
        }
        CP_COMMIT; CP_WAIT0;
        __syncthreads();
    }

    uint32_t qf[2][4][4];
    {
        uint32_t qs = smem_u32(sm.q);
        #pragma unroll
        for (int rt = 0; rt < 2; rt++)
            #pragma unroll
            for (int kc = 0; kc < 4; kc++) {
                int row = warp * 32 + rt * 16 + (lane & 15);
                uint32_t addr = qs + swz(row, kc * 2 + (lane >> 4));
                LDMX4(qf[rt][kc][0], qf[rt][kc][1], qf[rt][kc][2], qf[rt][kc][3], addr);
            }
    }
    __syncthreads();

    float o[2][8][4];
    #pragma unroll
    for (int rt = 0; rt < 2; rt++)
        #pragma unroll
        for (int nt = 0; nt < 8; nt++)
            #pragma unroll
            for (int r = 0; r < 4; r++) o[rt][nt][r] = 0.0f;
    float m_lo[2] = {-3.0e38f, -3.0e38f}, m_hi[2] = {-3.0e38f, -3.0e38f};
    float l_lo[2] = {0.0f, 0.0f},         l_hi[2] = {0.0f, 0.0f};

    auto kvload = [&](int stg, int c0) {
        uint32_t ks = smem_u32(sm.s.k[stg]);
        uint32_t vs = smem_u32(sm.s.v[stg]);
        #pragma unroll
        for (int i = 0; i < 4; i++) {
            int linear = i * 128 + tid;
            int r = linear >> 3, c16 = linear & 7;
            CP_ASYNC16(ks + swz(r, c16), K + base + (long)(c0 + r) * DM + c16 * 8);
        }
        #pragma unroll
        for (int i = 0; i < 4; i++) {
            int linear = i * 128 + tid;
            int r = linear >> 3, c16 = linear & 7;
            CP_ASYNC16(vs + swz(r, c16), V + base + (long)(c0 + r) * DM + c16 * 8);
        }
    };

    kvload(0, 0);
    CP_COMMIT;

    const int NT = SQ / 64;
    for (int t = 0; t < NT; t++) {
        if (t + 1 < NT) { kvload((t + 1) & 1, (t + 1) * 64); CP_COMMIT; CP_WAIT1; }
        else            { CP_WAIT0; }
        __syncthreads();

        const uint32_t ks = smem_u32(sm.s.k[t & 1]);
        const uint32_t vs = smem_u32(sm.s.v[t & 1]);

        float s[2][8][4];
        #pragma unroll
        for (int rt = 0; rt < 2; rt++)
            #pragma unroll
            for (int nt = 0; nt < 8; nt++)
                #pragma unroll
                for (int r = 0; r < 4; r++) s[rt][nt][r] = 0.0f;

        #pragma unroll
        for (int kc = 0; kc < 4; kc++) {
            uint32_t br[4][4];
            #pragma unroll
            for (int nt2 = 0; nt2 < 4; nt2++) {
                int row = nt2 * 16 + (lane & 15);
                uint32_t addr = ks + swz(row, kc * 2 + (lane >> 4));
                LDMX4(br[nt2][0], br[nt2][1], br[nt2][2], br[nt2][3], addr);
            }
            #pragma unroll
            for (int rt = 0; rt < 2; rt++)
                #pragma unroll
                for (int nt = 0; nt < 8; nt++)
                    MMA16816(s[rt][nt], qf[rt][kc],
                             br[nt >> 1][nt & 1], br[nt >> 1][(nt & 1) + 2]);
        }

        uint32_t pp[2][8][2];
        #pragma unroll
        for (int rt = 0; rt < 2; rt++) {
            float mt_lo = -3.0e38f, mt_hi = -3.0e38f;
            #pragma unroll
            for (int nt = 0; nt < 8; nt++) {
                mt_lo = fmaxf(mt_lo, fmaxf(s[rt][nt][0], s[rt][nt][1]));
                mt_hi = fmaxf(mt_hi, fmaxf(s[rt][nt][2], s[rt][nt][3]));
            }
            mt_lo *= 0.125f; mt_hi *= 0.125f;
            mt_lo = fmaxf(mt_lo, __shfl_xor_sync(0xffffffffu, mt_lo, 1));
            mt_lo = fmaxf(mt_lo, __shfl_xor_sync(0xffffffffu, mt_lo, 2));
            mt_hi = fmaxf(mt_hi, __shfl_xor_sync(0xffffffffu, mt_hi, 1));
            mt_hi = fmaxf(mt_hi, __shfl_xor_sync(0xffffffffu, mt_hi, 2));

            const float mn_lo = fmaxf(m_lo[rt], mt_lo);
            const float mn_hi = fmaxf(m_hi[rt], mt_hi);
            const float corr_lo = __expf(m_lo[rt] - mn_lo);
            const float corr_hi = __expf(m_hi[rt] - mn_hi);
            m_lo[rt] = mn_lo; m_hi[rt] = mn_hi;

            float rs_lo = 0.0f, rs_hi = 0.0f;
            #pragma unroll
            for (int nt = 0; nt < 8; nt++) {
                float p0 = __expf(fmaf(s[rt][nt][0], 0.125f, -mn_lo));
                float p1 = __expf(fmaf(s[rt][nt][1], 0.125f, -mn_lo));
                float p2 = __expf(fmaf(s[rt][nt][2], 0.125f, -mn_hi));
                float p3 = __expf(fmaf(s[rt][nt][3], 0.125f, -mn_hi));
                rs_lo += p0 + p1; rs_hi += p2 + p3;
                __half2 h01 = __floats2half2_rn(p0, p1);
                __half2 h23 = __floats2half2_rn(p2, p3);
                pp[rt][nt][0] = *(uint32_t*)&h01;
                pp[rt][nt][1] = *(uint32_t*)&h23;
            }
            rs_lo += __shfl_xor_sync(0xffffffffu, rs_lo, 1);
            rs_lo += __shfl_xor_sync(0xffffffffu, rs_lo, 2);
            rs_hi += __shfl_xor_sync(0xffffffffu, rs_hi, 1);
            rs_hi += __shfl_xor_sync(0xffffffffu, rs_hi, 2);
            l_lo[rt] = l_lo[rt] * corr_lo + rs_lo;
            l_hi[rt] = l_hi[rt] * corr_hi + rs_hi;
            #pragma unroll
            for (int nt = 0; nt < 8; nt++) {
                o[rt][nt][0] *= corr_lo; o[rt][nt][1] *= corr_lo;
                o[rt][nt][2] *= corr_hi; o[rt][nt][3] *= corr_hi;
            }
        }

        #pragma unroll
        for (int kc = 0; kc < 4; kc++) {
            uint32_t vr[4][4];
            #pragma unroll
            for (int g2 = 0; g2 < 4; g2++) {
                int row = kc * 16 + (lane & 15);
                uint32_t addr = vs + swz(row, g2 * 2 + (lane >> 4));
                LDMX4T(vr[g2][0], vr[g2][1], vr[g2][2], vr[g2][3], addr);
            }
            #pragma unroll
            for (int rt = 0; rt < 2; rt++) {
                uint32_t a[4] = { pp[rt][2 * kc][0], pp[rt][2 * kc][1],
                                  pp[rt][2 * kc + 1][0], pp[rt][2 * kc + 1][1] };
                #pragma unroll
                for (int nt = 0; nt < 8; nt++)
                    MMA16816(o[rt][nt], a,
                             vr[nt >> 1][(nt & 1) * 2], vr[nt >> 1][(nt & 1) * 2 + 1]);
            }
        }
        __syncthreads();
    }

    // ---- epilogue: fp16 ctx out
    #pragma unroll
    for (int rt = 0; rt < 2; rt++) {
        const float inv_lo = 1.0f / l_lo[rt], inv_hi = 1.0f / l_hi[rt];
        const long row_lo = q0 + warp * 32 + rt * 16 + (lane >> 2);
        #pragma unroll
        for (int nt = 0; nt < 8; nt++) {
            int col = nt * 8 + 2 * (lane & 3);
            *(__half2*)&O[base + row_lo * DM + col] =
                __floats2half2_rn(o[rt][nt][0] * inv_lo, o[rt][nt][1] * inv_lo);
            *(__half2*)&O[base + (row_lo + 8) * DM + col] =
                __floats2half2_rn(o[rt][nt][2] * inv_hi, o[rt][nt][3] * inv_hi);
        }
    }
}

// ---------------------------------------------------------------------------
// LayerNorm over rows of length 1024; optional secondary fp16 output.
// ---------------------------------------------------------------------------
template<bool DUAL>
__global__ void __launch_bounds__(256)
layernorm1024(const float* __restrict__ x, const float* __restrict__ g,
              const float* __restrict__ b, float* __restrict__ out,
              __half* __restrict__ out16)
{
    const long row = blockIdx.x;
    const float* p = x + row * (long)DM;
    float v[4];
    float s = 0.0f;
    #pragma unroll
    for (int i = 0; i < 4; i++) {
        v[i] = p[threadIdx.x + i * 256];
        s += v[i];
    }
    s = block_reduce_sum(s);
    const float mean = s * (1.0f / DM);
    float s2 = 0.0f;
    #pragma unroll
    for (int i = 0; i < 4; i++) {
        float d = v[i] - mean;
        s2 += d * d;
    }
    s2 = block_reduce_sum(s2);
    const float rstd = rsqrtf(s2 * (1.0f / DM) + 1e-5f);
    #pragma unroll
    for (int i = 0; i < 4; i++) {
        int c = threadIdx.x + i * 256;
        float y = (v[i] - mean) * rstd * g[c] + b[c];
        out[row * (long)DM + c] = y;
        if (DUAL) out16[row * (long)DM + c] = __float2half(y);
    }
}

// ---------------------------------------------------------------------------
// Launch orchestration (graph-capturable: kernel launches only)
// ---------------------------------------------------------------------------
extern "C" void kernel_launch(void* const* d_in, const int* in_sizes, int n_in,
                              void* d_out, int out_size)
{
    const float* src   = (const float*)d_in[0];
    const float* qw    = (const float*)d_in[1];
    const float* qb    = (const float*)d_in[2];
    const float* kw    = (const float*)d_in[3];
    const float* kb    = (const float*)d_in[4];
    const float* vw    = (const float*)d_in[5];
    const float* vb    = (const float*)d_in[6];
    const float* ow    = (const float*)d_in[7];
    const float* ob    = (const float*)d_in[8];
    const float* w1    = (const float*)d_in[9];
    const float* b1    = (const float*)d_in[10];
    const float* w2    = (const float*)d_in[11];
    const float* b2    = (const float*)d_in[12];
    const float* g1    = (const float*)d_in[13];
    const float* beta1 = (const float*)d_in[14];
    const float* g2    = (const float*)d_in[15];
    const float* beta2 = (const float*)d_in[16];
    float* out = (float*)d_out;

    __half *srch, *qwh, *kwh, *vwh, *owh, *w1h, *w2h;
    __half *qh, *kh, *vh, *ctxh, *x1h, *ffh;
    float  *t0, *t1, *t2;
    cudaGetSymbolAddress((void**)&srch, g_srch);
    cudaGetSymbolAddress((void**)&qwh,  g_qwh);
    cudaGetSymbolAddress((void**)&kwh,  g_kwh);
    cudaGetSymbolAddress((void**)&vwh,  g_vwh);
    cudaGetSymbolAddress((void**)&owh,  g_owh);
    cudaGetSymbolAddress((void**)&w1h,  g_w1h);
    cudaGetSymbolAddress((void**)&w2h,  g_w2h);
    cudaGetSymbolAddress((void**)&qh,   g_qh);
    cudaGetSymbolAddress((void**)&kh,   g_kh);
    cudaGetSymbolAddress((void**)&vh,   g_vh);
    cudaGetSymbolAddress((void**)&ctxh, g_ctxh);
    cudaGetSymbolAddress((void**)&x1h,  g_x1h);
    cudaGetSymbolAddress((void**)&ffh,  g_ffh);
    cudaGetSymbolAddress((void**)&t0,   g_t0);
    cudaGetSymbolAddress((void**)&t1,   g_t1);
    cudaGetSymbolAddress((void**)&t2,   g_t2);

    // enable 64 KB dynamic smem on the gemm16 instantiations (host-side,
    // immediate, idempotent, not a stream op — capture-safe)
    const int SMEM = 64 * 1024;
    cudaFuncSetAttribute(gemm16<false,false,__half>,
                         cudaFuncAttributeMaxDynamicSharedMemorySize, SMEM);
    cudaFuncSetAttribute(gemm16<false,true,float>,
                         cudaFuncAttributeMaxDynamicSharedMemorySize, SMEM);
    cudaFuncSetAttribute(gemm16<true,false,__half>,
                         cudaFuncAttributeMaxDynamicSharedMemorySize, SMEM);

    const dim3 blk(256);

    // ---- one-time fp16 conversions (src + weights)
    f32tof16<<<(MROWS * DM) / 1024, blk>>>(src, srch);
    f32tof16<<<(DM * DM) / 1024, blk>>>(qw, qwh);
    f32tof16<<<(DM * DM) / 1024, blk>>>(kw, kwh);
    f32tof16<<<(DM * DM) / 1024, blk>>>(vw, vwh);
    f32tof16<<<(DM * DM) / 1024, blk>>>(ow, owh);
    f32tof16<<<(FFD * DM) / 1024, blk>>>(w1, w1h);
    f32tof16<<<(DM * FFD) / 1024, blk>>>(w2, w2h);

    // ---- QKV projections (fp16 in, fp16 out)
    {
        dim3 g(DM / 128, MROWS / 128);
        gemm16<false,false,__half><<<g, blk, SMEM>>>(
            srch, DM, qwh, DM, qb, nullptr, qh, DM, MROWS, DM, DM);
        gemm16<false,false,__half><<<g, blk, SMEM>>>(
            srch, DM, kwh, DM, kb, nullptr, kh, DM, MROWS, DM, DM);
        gemm16<false,false,__half><<<g, blk, SMEM>>>(
            srch, DM, vwh, DM, vb, nullptr, vh, DM, MROWS, DM, DM);
    }

    // ---- fused attention: ctxh = softmax(QK^T/8) V (fp16 out)
    {
        dim3 g(SQ / 128, BZ * NH);
        flash_hmma<<<g, dim3(128)>>>(qh, kh, vh, ctxh);
    }

    // ---- O projection + residual: y(t1) = ctxh @ ow^T + ob + src
    {
        dim3 g(DM / 128, MROWS / 128);
        gemm16<false,true,float><<<g, blk, SMEM>>>(
            ctxh, DM, owh, DM, ob, src, t1, DM, MROWS, DM, DM);
    }

    // ---- LN1: x1 = LN(y) -> f32 (t2) + fp16 (x1h)
    layernorm1024<true><<<MROWS, blk>>>(t1, g1, beta1, t2, x1h);

    // ---- FF1: ffh = relu(x1h @ w1h^T + b1) (fp16 out)
    {
        dim3 g(FFD / 128, MROWS / 128);
        gemm16<true,false,__half><<<g, blk, SMEM>>>(
            x1h, DM, w1h, DM, b1, nullptr, ffh, FFD, MROWS, FFD, DM);
    }

    // ---- FF2 + residual: y2(t0) = ffh @ w2h^T + b2 + x1(t2)
    {
        dim3 g(DM / 128, MROWS / 128);
        gemm16<false,true,float><<<g, blk, SMEM>>>(
            ffh, FFD, w2h, FFD, b2, t2, t0, DM, MROWS, DM, FFD);
    }

    // ---- LN2 -> output
    layernorm1024<false><<<MROWS, blk>>>(t0, g2, beta2, out, nullptr);
}

// round 13
// speedup vs baseline: 8.5749x; 1.0270x over previous
#include <cuda_runtime.h>
#include <cuda_fp16.h>
#include <cstdint>

// ---------------------------------------------------------------------------
// Problem constants
// ---------------------------------------------------------------------------
#define BZ   2
#define SQ   2048
#define DM   1024
#define NH   16
#define DH   64
#define FFD  4096
#define MROWS (BZ * SQ)            // 4096

// ---------------------------------------------------------------------------
// Scratch (device globals).
// ---------------------------------------------------------------------------
__device__ __half g_srch [(size_t)MROWS * DM];          // src fp16
__device__ __half g_wqkvh[(size_t)3 * DM * DM];         // packed q/k/v weights
__device__ float  g_bqkv [(size_t)3 * DM];              // packed q/k/v bias
__device__ __half g_owh  [(size_t)DM * DM];
__device__ __half g_w1h  [(size_t)FFD * DM];
__device__ __half g_w2h  [(size_t)DM * FFD];
__device__ __half g_qkvh [(size_t)MROWS * 3 * DM];      // packed QKV activations
__device__ __half g_ctxh [(size_t)MROWS * DM];
__device__ __half g_x1h  [(size_t)MROWS * DM];
__device__ __half g_ffh  [(size_t)MROWS * FFD];
__device__ float  g_t1   [(size_t)MROWS * DM];          // y
__device__ float  g_t2   [(size_t)MROWS * DM];          // x1 f32 (FF2 resid)
__device__ float  g_t0   [(size_t)MROWS * DM];          // y2

// ---------------------------------------------------------------------------
// Helpers
// ---------------------------------------------------------------------------
__device__ __forceinline__ uint32_t smem_u32(const void* p) {
    return (uint32_t)__cvta_generic_to_shared(p);
}

#define LDMX4(r0, r1, r2, r3, addr)                                         \
    asm volatile("ldmatrix.sync.aligned.m8n8.x4.shared.b16 {%0,%1,%2,%3}, [%4];" \
                 : "=r"(r0), "=r"(r1), "=r"(r2), "=r"(r3) : "r"(addr))

#define LDMX4T(r0, r1, r2, r3, addr)                                        \
    asm volatile("ldmatrix.sync.aligned.m8n8.x4.trans.shared.b16 {%0,%1,%2,%3}, [%4];" \
                 : "=r"(r0), "=r"(r1), "=r"(r2), "=r"(r3) : "r"(addr))

#define MMA16816(d, a, b0, b1)                                              \
    asm volatile("mma.sync.aligned.m16n8k16.row.col.f32.f16.f16.f32 "        \
                 "{%0,%1,%2,%3}, {%4,%5,%6,%7}, {%8,%9}, {%0,%1,%2,%3};"     \
                 : "+f"(d[0]), "+f"(d[1]), "+f"(d[2]), "+f"(d[3])            \
                 : "r"(a[0]), "r"(a[1]), "r"(a[2]), "r"(a[3]),               \
                   "r"(b0), "r"(b1))

#define CP_ASYNC16(dst, src)                                                \
    asm volatile("cp.async.cg.shared.global [%0], [%1], 16;"                 \
                 :: "r"(dst), "l"(src))
#define CP_COMMIT  asm volatile("cp.async.commit_group;")
#define CP_WAIT0   asm volatile("cp.async.wait_group 0;")
#define CP_WAIT1   asm volatile("cp.async.wait_group 1;")

// swizzled byte offset within a 64-half-wide (128B) row tile
__device__ __forceinline__ uint32_t swz(int r, int c16) {
    return (uint32_t)(r * 128 + ((c16 ^ (r & 7)) * 16));
}

__device__ __forceinline__ void store2(float* C, long idx, float v0, float v1) {
    *(float2*)&C[idx] = make_float2(v0, v1);
}
__device__ __forceinline__ void store2(__half* C, long idx, float v0, float v1) {
    *(__half2*)&C[idx] = __floats2half2_rn(v0, v1);
}

__device__ __forceinline__ float block_reduce_sum(float v) {
    __shared__ float sh[32];
    const unsigned mask = 0xffffffffu;
    #pragma unroll
    for (int o = 16; o > 0; o >>= 1) v += __shfl_xor_sync(mask, v, o);
    int lane = threadIdx.x & 31, w = threadIdx.x >> 5;
    __syncthreads();
    if (lane == 0) sh[w] = v;
    __syncthreads();
    int nw = (blockDim.x + 31) >> 5;
    if (w == 0) {
        v = (lane < nw) ? sh[lane] : 0.0f;
        #pragma unroll
        for (int o = 16; o > 0; o >>= 1) v += __shfl_xor_sync(mask, v, o);
        if (lane == 0) sh[0] = v;
    }
    __syncthreads();
    return sh[0];
}

// ---------------------------------------------------------------------------
// One-shot segmented f32 -> f16 conversion of src + all weights.
// Segment layout (element offsets):
//   [0,4M) src | [4M,5M) qw | [5M,6M) kw | [6M,7M) vw | [7M,8M) ow
//   [8M,12M) w1 | [12M,16M) w2         (total 16,777,216 elements)
// ---------------------------------------------------------------------------
__global__ void __launch_bounds__(256)
convert_all(const float* __restrict__ src, const float* __restrict__ qw,
            const float* __restrict__ kw,  const float* __restrict__ vw,
            const float* __restrict__ ow,  const float* __restrict__ w1,
            const float* __restrict__ w2,
            __half* __restrict__ srch, __half* __restrict__ wqkv,
            __half* __restrict__ owh,  __half* __restrict__ w1h,
            __half* __restrict__ w2h)
{
    long i = ((long)blockIdx.x * 256 + threadIdx.x) * 4;
    const float* in; __half* out; long off;
    if      (i <  4194304L) { in = src; out = srch;           off = i; }
    else if (i <  5242880L) { in = qw;  out = wqkv;           off = i - 4194304L; }
    else if (i <  6291456L) { in = kw;  out = wqkv + 1048576; off = i - 5242880L; }
    else if (i <  7340032L) { in = vw;  out = wqkv + 2097152; off = i - 6291456L; }
    else if (i <  8388608L) { in = ow;  out = owh;            off = i - 7340032L; }
    else if (i < 12582912L) { in = w1;  out = w1h;            off = i - 8388608L; }
    else                    { in = w2;  out = w2h;            off = i - 12582912L; }
    float4 t = *(const float4*)&in[off];
    __half2* d = (__half2*)&out[off];
    d[0] = __floats2half2_rn(t.x, t.y);
    d[1] = __floats2half2_rn(t.z, t.w);
}

__global__ void __launch_bounds__(256)
pack_bias(const float* __restrict__ qb, const float* __restrict__ kb,
          const float* __restrict__ vb, float* __restrict__ out)
{
    int i = blockIdx.x * 256 + threadIdx.x;
    float v = (i < 1024) ? qb[i] : (i < 2048 ? kb[i - 1024] : vb[i - 2048]);
    out[i] = v;
}

// ---------------------------------------------------------------------------
// Pipelined fp16 GEMM (TN), 3-stage cp.async, ONE syncthreads per iter.
// C(OutT) = A @ B^T [+ bias(f32)] [+ resid(f32)], optional ReLU.
// A [M,K] fp16, B [N,K] fp16, K-major. fp32 accumulate. 256 thr,
// tile 128x128x64. Dynamic smem: 96 KB = 3 stages x (A 16KB + B 16KB).
// Iter t: wait(stage t) -> sync -> issue(stage t+2, which is (t-1)%3 and
// fully consumed before the sync) -> compute(stage t).
// ---------------------------------------------------------------------------
template<bool RELU, bool RESID, typename OutT>
__global__ void __launch_bounds__(256, 2)
gemm16(const __half* __restrict__ A, int lda,
       const __half* __restrict__ B, int ldb,
       const float* __restrict__ bias,
       const float* __restrict__ resid,
       OutT* __restrict__ C, int ldc,
       int M, int N, int K)
{
    extern __shared__ __half smem[];
    constexpr int STAGE = 2 * 128 * 64;   // halves per stage (A tile + B tile)

    const int tid  = threadIdx.x;
    const int warp = tid >> 5, lane = tid & 31;
    const int wm = warp >> 2;             // 0..1
    const int wn = warp & 3;              // 0..3
    const int row0 = blockIdx.y * 128;
    const int col0 = blockIdx.x * 128;

    auto load = [&](int stg, int k0) {
        uint32_t as = smem_u32(smem + stg * STAGE);
        uint32_t bs = smem_u32(smem + stg * STAGE + 128 * 64);
        #pragma unroll
        for (int i = 0; i < 4; i++) {
            int linear = i * 256 + tid;
            int r = linear >> 3, c16 = linear & 7;
            CP_ASYNC16(as + swz(r, c16), A + (long)(row0 + r) * lda + k0 + c16 * 8);
        }
        #pragma unroll
        for (int i = 0; i < 4; i++) {
            int linear = i * 256 + tid;
            int r = linear >> 3, c16 = linear & 7;
            CP_ASYNC16(bs + swz(r, c16), B + (long)(col0 + r) * ldb + k0 + c16 * 8);
        }
    };

    float acc[4][4][4];
    #pragma unroll
    for (int mt = 0; mt < 4; mt++)
        #pragma unroll
        for (int nt = 0; nt < 4; nt++)
            #pragma unroll
            for (int r = 0; r < 4; r++) acc[mt][nt][r] = 0.0f;

    const int NSTEP = K / 64;
    load(0, 0);  CP_COMMIT;
    load(1, 64); CP_COMMIT;

    for (int t = 0; t < NSTEP; t++) {
        if (t < NSTEP - 1) { CP_WAIT1; } else { CP_WAIT0; }
        __syncthreads();
        if (t + 2 < NSTEP) { load((t + 2) % 3, (t + 2) * 64); CP_COMMIT; }

        const uint32_t as = smem_u32(smem + (t % 3) * STAGE);
        const uint32_t bs = smem_u32(smem + (t % 3) * STAGE + 128 * 64);

        #pragma unroll
        for (int ks = 0; ks < 4; ks++) {
            uint32_t a[4][4], br[2][4];
            #pragma unroll
            for (int mt = 0; mt < 4; mt++) {
                int row = wm * 64 + mt * 16 + (lane & 15);
                uint32_t addr = as + swz(row, ks * 2 + (lane >> 4));
                LDMX4(a[mt][0], a[mt][1], a[mt][2], a[mt][3], addr);
            }
            #pragma unroll
            for (int nt2 = 0; nt2 < 2; nt2++) {
                int row = wn * 32 + nt2 * 16 + (lane & 15);
                uint32_t addr = bs + swz(row, ks * 2 + (lane >> 4));
                LDMX4(br[nt2][0], br[nt2][1], br[nt2][2], br[nt2][3], addr);
            }
            #pragma unroll
            for (int mt = 0; mt < 4; mt++)
                #pragma unroll
                for (int nt = 0; nt < 4; nt++) {
                    uint32_t b0 = br[nt >> 1][(nt & 1)];
                    uint32_t b1 = br[nt >> 1][(nt & 1) + 2];
                    MMA16816(acc[mt][nt], a[mt], b0, b1);
                }
        }
    }

    #pragma unroll
    for (int mt = 0; mt < 4; mt++) {
        int r0w = row0 + wm * 64 + mt * 16 + (lane >> 2);
        #pragma unroll
        for (int nt = 0; nt < 4; nt++) {
            int cn = col0 + wn * 32 + nt * 8 + 2 * (lane & 3);
            float v0 = acc[mt][nt][0], v1 = acc[mt][nt][1];
            float v2 = acc[mt][nt][2], v3 = acc[mt][nt][3];
            if (bias) {
                float b0v = bias[cn], b1v = bias[cn + 1];
                v0 += b0v; v1 += b1v; v2 += b0v; v3 += b1v;
            }
            if (RESID) {
                v0 += resid[(long)r0w * ldc + cn];
                v1 += resid[(long)r0w * ldc + cn + 1];
                v2 += resid[(long)(r0w + 8) * ldc + cn];
                v3 += resid[(long)(r0w + 8) * ldc + cn + 1];
            }
            if (RELU) {
                v0 = fmaxf(v0, 0.0f); v1 = fmaxf(v1, 0.0f);
                v2 = fmaxf(v2, 0.0f); v3 = fmaxf(v3, 0.0f);
            }
            store2(C, (long)r0w * ldc + cn, v0, v1);
            store2(C, (long)(r0w + 8) * ldc + cn, v2, v3);
        }
    }
}

// ---------------------------------------------------------------------------
// Flash attention v3 (R11-proven) with input row stride lda (packed QKV).
// 128 threads (4 warps x 32 query rows), BR=128, BC=64, cp.async + swizzle,
// ldmatrix.trans for V, double-buffered K/V stages. fp16 ctx out (stride DM).
// ---------------------------------------------------------------------------
__global__ void __launch_bounds__(128)
flash_hmma(const __half* __restrict__ Q, const __half* __restrict__ K,
           const __half* __restrict__ V, int lda, __half* __restrict__ O)
{
    __shared__ __align__(16) union SmemU {
        __half q[128 * 64];
        struct { __half k[2][64 * 64]; __half v[2][64 * 64]; } s;
    } sm;

    const int bh = blockIdx.y;
    const int b  = bh / NH, h = bh % NH;
    const int q0 = blockIdx.x * 128;
    const long baseIn  = (long)b * SQ * lda + (long)h * DH;
    const long baseOut = (long)b * SQ * DM  + (long)h * DH;

    const int tid  = threadIdx.x;
    const int warp = tid >> 5, lane = tid & 31;

    {
        uint32_t qs = smem_u32(sm.q);
        #pragma unroll
        for (int i = 0; i < 8; i++) {
            int linear = i * 128 + tid;
            int r = linear >> 3, c16 = linear & 7;
            CP_ASYNC16(qs + swz(r, c16),
                       Q + baseIn + (long)(q0 + r) * lda + c16 * 8);
        }
        CP_COMMIT; CP_WAIT0;
        __syncthreads();
    }

    uint32_t qf[2][4][4];
    {
        uint32_t qs = smem_u32(sm.q);
        #pragma unroll
        for (int rt = 0; rt < 2; rt++)
            #pragma unroll
            for (int kc = 0; kc < 4; kc++) {
                int row = warp * 32 + rt * 16 + (lane & 15);
                uint32_t addr = qs + swz(row, kc * 2 + (lane >> 4));
                LDMX4(qf[rt][kc][0], qf[rt][kc][1], qf[rt][kc][2], qf[rt][kc][3], addr);
            }
    }
    __syncthreads();

    float o[2][8][4];
    #pragma unroll
    for (int rt = 0; rt < 2; rt++)
        #pragma unroll
        for (int nt = 0; nt < 8; nt++)
            #pragma unroll
            for (int r = 0; r < 4; r++) o[rt][nt][r] = 0.0f;
    float m_lo[2] = {-3.0e38f, -3.0e38f}, m_hi[2] = {-3.0e38f, -3.0e38f};
    float l_lo[2] = {0.0f, 0.0f},         l_hi[2] = {0.0f, 0.0f};

    auto kvload = [&](int stg, int c0) {
        uint32_t ks = smem_u32(sm.s.k[stg]);
        uint32_t vs = smem_u32(sm.s.v[stg]);
        #pragma unroll
        for (int i = 0; i < 4; i++) {
            int linear = i * 128 + tid;
            int r = linear >> 3, c16 = linear & 7;
            CP_ASYNC16(ks + swz(r, c16), K + baseIn + (long)(c0 + r) * lda + c16 * 8);
        }
        #pragma unroll
        for (int i = 0; i < 4; i++) {
            int linear = i * 128 + tid;
            int r = linear >> 3, c16 = linear & 7;
            CP_ASYNC16(vs + swz(r, c16), V + baseIn + (long)(c0 + r) * lda + c16 * 8);
        }
    };

    kvload(0, 0);
    CP_COMMIT;

    const int NT = SQ / 64;
    for (int t = 0; t < NT; t++) {
        if (t + 1 < NT) { kvload((t + 1) & 1, (t + 1) * 64); CP_COMMIT; CP_WAIT1; }
        else            { CP_WAIT0; }
        __syncthreads();

        const uint32_t ks = smem_u32(sm.s.k[t & 1]);
        const uint32_t vs = smem_u32(sm.s.v[t & 1]);

        float s[2][8][4];
        #pragma unroll
        for (int rt = 0; rt < 2; rt++)
            #pragma unroll
            for (int nt = 0; nt < 8; nt++)
                #pragma unroll
                for (int r = 0; r < 4; r++) s[rt][nt][r] = 0.0f;

        #pragma unroll
        for (int kc = 0; kc < 4; kc++) {
            uint32_t br[4][4];
            #pragma unroll
            for (int nt2 = 0; nt2 < 4; nt2++) {
                int row = nt2 * 16 + (lane & 15);
                uint32_t addr = ks + swz(row, kc * 2 + (lane >> 4));
                LDMX4(br[nt2][0], br[nt2][1], br[nt2][2], br[nt2][3], addr);
            }
            #pragma unroll
            for (int rt = 0; rt < 2; rt++)
                #pragma unroll
                for (int nt = 0; nt < 8; nt++)
                    MMA16816(s[rt][nt], qf[rt][kc],
                             br[nt >> 1][nt & 1], br[nt >> 1][(nt & 1) + 2]);
        }

        uint32_t pp[2][8][2];
        #pragma unroll
        for (int rt = 0; rt < 2; rt++) {
            float mt_lo = -3.0e38f, mt_hi = -3.0e38f;
            #pragma unroll
            for (int nt = 0; nt < 8; nt++) {
                mt_lo = fmaxf(mt_lo, fmaxf(s[rt][nt][0], s[rt][nt][1]));
                mt_hi = fmaxf(mt_hi, fmaxf(s[rt][nt][2], s[rt][nt][3]));
            }
            mt_lo *= 0.125f; mt_hi *= 0.125f;
            mt_lo = fmaxf(mt_lo, __shfl_xor_sync(0xffffffffu, mt_lo, 1));
            mt_lo = fmaxf(mt_lo, __shfl_xor_sync(0xffffffffu, mt_lo, 2));
            mt_hi = fmaxf(mt_hi, __shfl_xor_sync(0xffffffffu, mt_hi, 1));
            mt_hi = fmaxf(mt_hi, __shfl_xor_sync(0xffffffffu, mt_hi, 2));

            const float mn_lo = fmaxf(m_lo[rt], mt_lo);
            const float mn_hi = fmaxf(m_hi[rt], mt_hi);
            const float corr_lo = __expf(m_lo[rt] - mn_lo);
            const float corr_hi = __expf(m_hi[rt] - mn_hi);
            m_lo[rt] = mn_lo; m_hi[rt] = mn_hi;

            float rs_lo = 0.0f, rs_hi = 0.0f;
            #pragma unroll
            for (int nt = 0; nt < 8; nt++) {
                float p0 = __expf(fmaf(s[rt][nt][0], 0.125f, -mn_lo));
                float p1 = __expf(fmaf(s[rt][nt][1], 0.125f, -mn_lo));
                float p2 = __expf(fmaf(s[rt][nt][2], 0.125f, -mn_hi));
                float p3 = __expf(fmaf(s[rt][nt][3], 0.125f, -mn_hi));
                rs_lo += p0 + p1; rs_hi += p2 + p3;
                __half2 h01 = __floats2half2_rn(p0, p1);
                __half2 h23 = __floats2half2_rn(p2, p3);
                pp[rt][nt][0] = *(uint32_t*)&h01;
                pp[rt][nt][1] = *(uint32_t*)&h23;
            }
            rs_lo += __shfl_xor_sync(0xffffffffu, rs_lo, 1);
            rs_lo += __shfl_xor_sync(0xffffffffu, rs_lo, 2);
            rs_hi += __shfl_xor_sync(0xffffffffu, rs_hi, 1);
            rs_hi += __shfl_xor_sync(0xffffffffu, rs_hi, 2);
            l_lo[rt] = l_lo[rt] * corr_lo + rs_lo;
            l_hi[rt] = l_hi[rt] * corr_hi + rs_hi;
            #pragma unroll
            for (int nt = 0; nt < 8; nt++) {
                o[rt][nt][0] *= corr_lo; o[rt][nt][1] *= corr_lo;
                o[rt][nt][2] *= corr_hi; o[rt][nt][3] *= corr_hi;
            }
        }

        #pragma unroll
        for (int kc = 0; kc < 4; kc++) {
            uint32_t vr[4][4];
            #pragma unroll
            for (int g2 = 0; g2 < 4; g2++) {
                int row = kc * 16 + (lane & 15);
                uint32_t addr = vs + swz(row, g2 * 2 + (lane >> 4));
                LDMX4T(vr[g2][0], vr[g2][1], vr[g2][2], vr[g2][3], addr);
            }
            #pragma unroll
            for (int rt = 0; rt < 2; rt++) {
                uint32_t a[4] = { pp[rt][2 * kc][0], pp[rt][2 * kc][1],
                                  pp[rt][2 * kc + 1][0], pp[rt][2 * kc + 1][1] };
                #pragma unroll
                for (int nt = 0; nt < 8; nt++)
                    MMA16816(o[rt][nt], a,
                             vr[nt >> 1][(nt & 1) * 2], vr[nt >> 1][(nt & 1) * 2 + 1]);
            }
        }
        __syncthreads();
    }

    #pragma unroll
    for (int rt = 0; rt < 2; rt++) {
        const float inv_lo = 1.0f / l_lo[rt], inv_hi = 1.0f / l_hi[rt];
        const long row_lo = q0 + warp * 32 + rt * 16 + (lane >> 2);
        #pragma unroll
        for (int nt = 0; nt < 8; nt++) {
            int col = nt * 8 + 2 * (lane & 3);
            *(__half2*)&O[baseOut + row_lo * DM + col] =
                __floats2half2_rn(o[rt][nt][0] * inv_lo, o[rt][nt][1] * inv_lo);
            *(__half2*)&O[baseOut + (row_lo + 8) * DM + col] =
                __floats2half2_rn(o[rt][nt][2] * inv_hi, o[rt][nt][3] * inv_hi);
        }
    }
}

// ---------------------------------------------------------------------------
// LayerNorm over rows of length 1024; optional secondary fp16 output.
// ---------------------------------------------------------------------------
template<bool DUAL>
__global__ void __launch_bounds__(256)
layernorm1024(const float* __restrict__ x, const float* __restrict__ g,
              const float* __restrict__ b, float* __restrict__ out,
              __half* __restrict__ out16)
{
    const long row = blockIdx.x;
    const float* p = x + row * (long)DM;
    float v[4];
    float s = 0.0f;
    #pragma unroll
    for (int i = 0; i < 4; i++) {
        v[i] = p[threadIdx.x + i * 256];
        s += v[i];
    }
    s = block_reduce_sum(s);
    const float mean = s * (1.0f / DM);
    float s2 = 0.0f;
    #pragma unroll
    for (int i = 0; i < 4; i++) {
        float d = v[i] - mean;
        s2 += d * d;
    }
    s2 = block_reduce_sum(s2);
    const float rstd = rsqrtf(s2 * (1.0f / DM) + 1e-5f);
    #pragma unroll
    for (int i = 0; i < 4; i++) {
        int c = threadIdx.x + i * 256;
        float y = (v[i] - mean) * rstd * g[c] + b[c];
        out[row * (long)DM + c] = y;
        if (DUAL) out16[row * (long)DM + c] = __float2half(y);
    }
}

// ---------------------------------------------------------------------------
// Launch orchestration (graph-capturable: kernel launches only)
// ---------------------------------------------------------------------------
extern "C" void kernel_launch(void* const* d_in, const int* in_sizes, int n_in,
                              void* d_out, int out_size)
{
    const float* src   = (const float*)d_in[0];
    const float* qw    = (const float*)d_in[1];
    const float* qb    = (const float*)d_in[2];
    const float* kw    = (const float*)d_in[3];
    const float* kb    = (const float*)d_in[4];
    const float* vw    = (const float*)d_in[5];
    const float* vb    = (const float*)d_in[6];
    const float* ow    = (const float*)d_in[7];
    const float* ob    = (const float*)d_in[8];
    const float* w1    = (const float*)d_in[9];
    const float* b1    = (const float*)d_in[10];
    const float* w2    = (const float*)d_in[11];
    const float* b2    = (const float*)d_in[12];
    const float* g1    = (const float*)d_in[13];
    const float* beta1 = (const float*)d_in[14];
    const float* g2    = (const float*)d_in[15];
    const float* beta2 = (const float*)d_in[16];
    float* out = (float*)d_out;

    __half *srch, *wqkvh, *owh, *w1h, *w2h, *qkvh, *ctxh, *x1h, *ffh;
    float  *bqkv, *t0, *t1, *t2;
    cudaGetSymbolAddress((void**)&srch,  g_srch);
    cudaGetSymbolAddress((void**)&wqkvh, g_wqkvh);
    cudaGetSymbolAddress((void**)&bqkv,  g_bqkv);
    cudaGetSymbolAddress((void**)&owh,   g_owh);
    cudaGetSymbolAddress((void**)&w1h,   g_w1h);
    cudaGetSymbolAddress((void**)&w2h,   g_w2h);
    cudaGetSymbolAddress((void**)&qkvh,  g_qkvh);
    cudaGetSymbolAddress((void**)&ctxh,  g_ctxh);
    cudaGetSymbolAddress((void**)&x1h,   g_x1h);
    cudaGetSymbolAddress((void**)&ffh,   g_ffh);
    cudaGetSymbolAddress((void**)&t0,    g_t0);
    cudaGetSymbolAddress((void**)&t1,    g_t1);
    cudaGetSymbolAddress((void**)&t2,    g_t2);

    // 96 KB dynamic smem for the 3-stage gemm (host-side, capture-safe)
    const int SMEM = 96 * 1024;
    cudaFuncSetAttribute(gemm16<false,false,__half>,
                         cudaFuncAttributeMaxDynamicSharedMemorySize, SMEM);
    cudaFuncSetAttribute(gemm16<false,true,float>,
                         cudaFuncAttributeMaxDynamicSharedMemorySize, SMEM);
    cudaFuncSetAttribute(gemm16<true,false,__half>,
                         cudaFuncAttributeMaxDynamicSharedMemorySize, SMEM);

    const dim3 blk(256);

    // ---- one-shot conversions
    convert_all<<<16384, blk>>>(src, qw, kw, vw, ow, w1, w2,
                                srch, wqkvh, owh, w1h, w2h);
    pack_bias<<<12, blk>>>(qb, kb, vb, bqkv);

    // ---- fused QKV projection: qkv[4096, 3072] = srch @ wqkv^T + bqkv
    {
        dim3 g(3 * DM / 128, MROWS / 128);
        gemm16<false,false,__half><<<g, blk, SMEM>>>(
            srch, DM, wqkvh, DM, bqkv, nullptr, qkvh, 3 * DM, MROWS, 3 * DM, DM);
    }

    // ---- fused attention on packed QKV (lda = 3*DM); ctxh fp16 out
    {
        dim3 g(SQ / 128, BZ * NH);
        flash_hmma<<<g, dim3(128)>>>(qkvh, qkvh + DM, qkvh + 2 * DM, 3 * DM, ctxh);
    }

    // ---- O projection + residual: y(t1) = ctxh @ ow^T + ob + src
    {
        dim3 g(DM / 128, MROWS / 128);
        gemm16<false,true,float><<<g, blk, SMEM>>>(
            ctxh, DM, owh, DM, ob, src, t1, DM, MROWS, DM, DM);
    }

    // ---- LN1: x1 = LN(y) -> f32 (t2) + fp16 (x1h)
    layernorm1024<true><<<MROWS, blk>>>(t1, g1, beta1, t2, x1h);

    // ---- FF1: ffh = relu(x1h @ w1h^T + b1) (fp16 out)
    {
        dim3 g(FFD / 128, MROWS / 128);
        gemm16<true,false,__half><<<g, blk, SMEM>>>(
            x1h, DM, w1h, DM, b1, nullptr, ffh, FFD, MROWS, FFD, DM);
    }

    // ---- FF2 + residual: y2(t0) = ffh @ w2h^T + b2 + x1(t2)
    {
        dim3 g(DM / 128, MROWS / 128);
        gemm16<false,true,float><<<g, blk, SMEM>>>(
            ffh, FFD, w2h, FFD, b2, t2, t0, DM, MROWS, DM, FFD);
    }

    // ---- LN2 -> output
    layernorm1024<false><<<MROWS, blk>>>(t0, g2, beta2, out, nullptr);
}